// round 1
// baseline (speedup 1.0000x reference)
#include <cuda_runtime.h>
#include <math.h>

#define NU 50000
#define NI 50000
#define DD 128
#define EE 800000
#define NT (NU + NI)

// ---------------- scratch (__device__ globals: no allocation allowed) ----------------
__device__ float g_P1u[NU * DD];           // feat_user @ W1^T + b1
__device__ float g_P1i[NI * DD];           // feat_item @ W1^T + b1
__device__ float g_as_u[NU], g_ad_u[NU];   // feat_user . attn[:D], feat_user . attn[D:]
__device__ float g_as_i[NI], g_ad_i[NI];
__device__ float g_ex1[EE], g_ex2[EE];     // logits, then exp(a - max)
__device__ float g_max_u[NU], g_max_i[NI];
__device__ float g_den_u[NU], g_den_i[NI];

__device__ __forceinline__ float leakyf(float x) { return x >= 0.f ? x : 0.2f * x; }

__device__ __forceinline__ void atomicMaxF(float* addr, float v) {
    if (v >= 0.f) atomicMax((int*)addr, __float_as_int(v));
    else          atomicMin((unsigned int*)addr, __float_as_uint(v));
}

__device__ __forceinline__ void red4(float* p, float a, float b, float c, float d) {
    asm volatile("red.global.add.v4.f32 [%0], {%1,%2,%3,%4};"
                 :: "l"(p), "f"(a), "f"(b), "f"(c), "f"(d) : "memory");
}

// ---------------- K0: init segment-max / denom ----------------
__global__ void k_init() {
    int i = blockIdx.x * blockDim.x + threadIdx.x;
    if (i < NU) {
        g_max_u[i] = -INFINITY; g_den_u[i] = 0.f;
        g_max_i[i] = -INFINITY; g_den_i[i] = 0.f;
    }
}

// ---------------- K1: node transform P1 = feat @ W1^T + b1 (also seeds h in d_out) ----------------
// 64 rows per block, 256 threads; thread = (eg,og) computes 4 rows x 8 outs.
__global__ __launch_bounds__(256) void k_node(const float* __restrict__ fu,
                                              const float* __restrict__ fi,
                                              const float* __restrict__ W1,
                                              const float* __restrict__ b1,
                                              float* __restrict__ out) {
    const int t = threadIdx.x;
    const int eg = t >> 4, og = t & 15;
    const int rowBase = blockIdx.x * 64;

    __shared__ float fs[64][36];    // row-padded to 36 (16B aligned rows)
    __shared__ float ws[32][132];   // W1^T chunk: ws[k][o]
    __shared__ float b1s[128];
    if (t < 128) b1s[t] = b1[t];

    float acc[4][8];
#pragma unroll
    for (int i = 0; i < 4; i++)
#pragma unroll
        for (int j = 0; j < 8; j++) acc[i][j] = 0.f;

    for (int kc = 0; kc < 128; kc += 32) {
        // stage feat tile (zero-fill out-of-range rows)
        for (int idx = t; idx < 512; idx += 256) {
            int r = idx >> 3, c4 = idx & 7;
            int row = rowBase + r;
            float4 v = make_float4(0.f, 0.f, 0.f, 0.f);
            if (row < NT) {
                const float* f = (row < NU) ? (fu + (size_t)row * DD)
                                            : (fi + (size_t)(row - NU) * DD);
                v = *(const float4*)(f + kc + c4 * 4);
            }
            *(float4*)&fs[r][c4 * 4] = v;
        }
        // stage W1^T chunk (coalesced global read along k)
        for (int idx = t; idx < 4096; idx += 256) {
            int o = idx >> 5, k = idx & 31;
            ws[k][o] = W1[o * DD + kc + k];
        }
        __syncthreads();
#pragma unroll
        for (int k = 0; k < 32; k++) {
            float z[4];
#pragma unroll
            for (int i = 0; i < 4; i++) z[i] = fs[eg * 4 + i][k];
            float w[8];
            *(float4*)&w[0] = *(const float4*)&ws[k][og * 8];
            *(float4*)&w[4] = *(const float4*)&ws[k][og * 8 + 4];
#pragma unroll
            for (int i = 0; i < 4; i++)
#pragma unroll
                for (int j = 0; j < 8; j++) acc[i][j] += z[i] * w[j];
        }
        __syncthreads();
    }

#pragma unroll
    for (int i = 0; i < 4; i++) {
        int row = rowBase + eg * 4 + i;
        if (row >= NT) continue;
        float o8[8];
#pragma unroll
        for (int j = 0; j < 8; j++) o8[j] = acc[i][j] + b1s[og * 8 + j];
        float* p1 = (row < NU) ? (g_P1u + (size_t)row * DD)
                               : (g_P1i + (size_t)(row - NU) * DD);
        *(float4*)(p1 + og * 8)     = *(float4*)&o8[0];
        *(float4*)(p1 + og * 8 + 4) = *(float4*)&o8[4];
        float* ho = out + (size_t)row * DD;  // h_user then h_item, contiguous
        *(float4*)(ho + og * 8)     = *(float4*)&o8[0];
        *(float4*)(ho + og * 8 + 4) = *(float4*)&o8[4];
    }
}

// ---------------- K1b: per-node attention dots ----------------
__global__ __launch_bounds__(256) void k_attn(const float* __restrict__ fu,
                                              const float* __restrict__ fi,
                                              const float* __restrict__ attn) {
    __shared__ float at[256];
    int t = threadIdx.x;
    at[t] = attn[t];
    __syncthreads();
    int gwarp = (blockIdx.x * 256 + t) >> 5;
    int lane = t & 31;
    if (gwarp >= NT) return;
    const float* f = (gwarp < NU) ? (fu + (size_t)gwarp * DD)
                                  : (fi + (size_t)(gwarp - NU) * DD);
    float4 v = *(const float4*)(f + lane * 4);
    float4 a1 = *(const float4*)&at[lane * 4];
    float4 a2 = *(const float4*)&at[128 + lane * 4];
    float s = v.x * a1.x + v.y * a1.y + v.z * a1.z + v.w * a1.w;
    float d = v.x * a2.x + v.y * a2.y + v.z * a2.z + v.w * a2.w;
#pragma unroll
    for (int m = 16; m > 0; m >>= 1) {
        s += __shfl_xor_sync(0xffffffffu, s, m);
        d += __shfl_xor_sync(0xffffffffu, d, m);
    }
    if (lane == 0) {
        if (gwarp < NU) { g_as_u[gwarp] = s; g_ad_u[gwarp] = d; }
        else            { g_as_i[gwarp - NU] = s; g_ad_i[gwarp - NU] = d; }
    }
}

// ---------------- K2: edge logits + segment max ----------------
__global__ void k_logits(const int* __restrict__ src, const int* __restrict__ dst) {
    int e = blockIdx.x * blockDim.x + threadIdx.x;
    if (e >= EE) return;
    int s = src[e], d = dst[e];
    float a1 = leakyf(g_as_u[s] + g_ad_i[d]);   // etype user->item, segments over item (d)
    float a2 = leakyf(g_as_i[d] + g_ad_u[s]);   // etype item->user, segments over user (s)
    g_ex1[e] = a1;
    g_ex2[e] = a2;
    atomicMaxF(&g_max_i[d], a1);
    atomicMaxF(&g_max_u[s], a2);
}

// ---------------- K3: exp + segment denom ----------------
__global__ void k_exp(const int* __restrict__ src, const int* __restrict__ dst) {
    int e = blockIdx.x * blockDim.x + threadIdx.x;
    if (e >= EE) return;
    int s = src[e], d = dst[e];
    float e1 = expf(g_ex1[e] - g_max_i[d]);
    float e2 = expf(g_ex2[e] - g_max_u[s]);
    g_ex1[e] = e1;
    g_ex2[e] = e2;
    atomicAdd(&g_den_i[d], e1);
    atomicAdd(&g_den_u[s], e2);
}

// ---------------- K4: edge kernel — Z2=(xs*xd)@W2^T, scatter both etypes ----------------
// 64 edges/block (EE % 64 == 0), 256 threads, thread=(eg,og): 4 edges x 8 outs.
__global__ __launch_bounds__(256) void k_edge(const float* __restrict__ fu,
                                              const float* __restrict__ fi,
                                              const int* __restrict__ src,
                                              const int* __restrict__ dst,
                                              const float* __restrict__ nui,
                                              const float* __restrict__ niu,
                                              const float* __restrict__ W2,
                                              const float* __restrict__ b2,
                                              float* __restrict__ out) {
    const int t = threadIdx.x;
    const int eg = t >> 4, og = t & 15;
    const int base = blockIdx.x * 64;

    __shared__ int   ss[64], sd[64];
    __shared__ float sw1[64], sw2[64];
    __shared__ float zc[64][36];
    __shared__ float wc[32][132];
    __shared__ float b2s[128];

    if (t < 64) {
        int e = base + t;
        int s = src[e], d = dst[e];
        ss[t] = s; sd[t] = d;
        sw1[t] = g_ex1[e] / g_den_i[d] * nui[e];   // alpha1 * norm_ui
        sw2[t] = g_ex2[e] / g_den_u[s] * niu[e];   // alpha2 * norm_iu
    }
    if (t < 128) b2s[t] = b2[t];
    __syncthreads();

    float acc[4][8];
#pragma unroll
    for (int i = 0; i < 4; i++)
#pragma unroll
        for (int j = 0; j < 8; j++) acc[i][j] = 0.f;

    for (int kc = 0; kc < 128; kc += 32) {
        // stage z chunk = feat_user[src]*feat_item[dst] (gather, coalesced per row)
        for (int idx = t; idx < 512; idx += 256) {
            int r = idx >> 3, c4 = idx & 7;
            float4 a = *(const float4*)(fu + (size_t)ss[r] * DD + kc + c4 * 4);
            float4 b = *(const float4*)(fi + (size_t)sd[r] * DD + kc + c4 * 4);
            float4 z;
            z.x = a.x * b.x; z.y = a.y * b.y; z.z = a.z * b.z; z.w = a.w * b.w;
            *(float4*)&zc[r][c4 * 4] = z;
        }
        // stage W2^T chunk
        for (int idx = t; idx < 4096; idx += 256) {
            int o = idx >> 5, k = idx & 31;
            wc[k][o] = W2[o * DD + kc + k];
        }
        __syncthreads();
#pragma unroll
        for (int k = 0; k < 32; k++) {
            float z[4];
#pragma unroll
            for (int i = 0; i < 4; i++) z[i] = zc[eg * 4 + i][k];
            float w[8];
            *(float4*)&w[0] = *(const float4*)&wc[k][og * 8];
            *(float4*)&w[4] = *(const float4*)&wc[k][og * 8 + 4];
#pragma unroll
            for (int i = 0; i < 4; i++)
#pragma unroll
                for (int j = 0; j < 8; j++) acc[i][j] += z[i] * w[j];
        }
        __syncthreads();
    }

    float* hu = out;                       // h_user accumulator
    float* hi = out + (size_t)NU * DD;     // h_item accumulator
    const int co = og * 8;
#pragma unroll
    for (int i = 0; i < 4; i++) {
        int el = eg * 4 + i;
        int s = ss[el], d = sd[el];
        float w1 = sw1[el], w2 = sw2[el];
        float z2[8];
#pragma unroll
        for (int j = 0; j < 8; j++) z2[j] = acc[i][j] + b2s[co + j];
        float4 pua = *(const float4*)(g_P1u + (size_t)s * DD + co);
        float4 pub = *(const float4*)(g_P1u + (size_t)s * DD + co + 4);
        float4 pia = *(const float4*)(g_P1i + (size_t)d * DD + co);
        float4 pib = *(const float4*)(g_P1i + (size_t)d * DD + co + 4);
        // h_item[d] += alpha1*norm_ui*(P1u[s] + Z2)
        red4(hi + (size_t)d * DD + co,
             w1 * (pua.x + z2[0]), w1 * (pua.y + z2[1]),
             w1 * (pua.z + z2[2]), w1 * (pua.w + z2[3]));
        red4(hi + (size_t)d * DD + co + 4,
             w1 * (pub.x + z2[4]), w1 * (pub.y + z2[5]),
             w1 * (pub.z + z2[6]), w1 * (pub.w + z2[7]));
        // h_user[s] += alpha2*norm_iu*(P1i[d] + Z2)
        red4(hu + (size_t)s * DD + co,
             w2 * (pia.x + z2[0]), w2 * (pia.y + z2[1]),
             w2 * (pia.z + z2[2]), w2 * (pia.w + z2[3]));
        red4(hu + (size_t)s * DD + co + 4,
             w2 * (pib.x + z2[4]), w2 * (pib.y + z2[5]),
             w2 * (pib.z + z2[6]), w2 * (pib.w + z2[7]));
    }
}

// ---------------- K5: leaky + L2 normalize (in place on d_out) ----------------
__global__ __launch_bounds__(256) void k_finish(float* __restrict__ out) {
    int gwarp = (blockIdx.x * 256 + threadIdx.x) >> 5;
    int lane = threadIdx.x & 31;
    if (gwarp >= NT) return;
    float* p = out + (size_t)gwarp * DD;
    float4 v = *(float4*)(p + lane * 4);
    v.x = leakyf(v.x); v.y = leakyf(v.y); v.z = leakyf(v.z); v.w = leakyf(v.w);
    float s = v.x * v.x + v.y * v.y + v.z * v.z + v.w * v.w;
#pragma unroll
    for (int m = 16; m > 0; m >>= 1) s += __shfl_xor_sync(0xffffffffu, s, m);
    float n = sqrtf(s);
    float inv = 1.f / fmaxf(n, 1e-12f);
    v.x *= inv; v.y *= inv; v.z *= inv; v.w *= inv;
    *(float4*)(p + lane * 4) = v;
}

// ---------------- launch ----------------
extern "C" void kernel_launch(void* const* d_in, const int* in_sizes, int n_in,
                              void* d_out, int out_size) {
    const float* fu   = (const float*)d_in[0];
    const float* fi   = (const float*)d_in[1];
    const int*   src  = (const int*)d_in[2];
    const int*   dst  = (const int*)d_in[3];
    const float* nui  = (const float*)d_in[4];
    const float* niu  = (const float*)d_in[5];
    const float* W1   = (const float*)d_in[6];
    const float* b1   = (const float*)d_in[7];
    const float* W2   = (const float*)d_in[8];
    const float* b2   = (const float*)d_in[9];
    const float* attn = (const float*)d_in[10];
    float* out = (float*)d_out;

    k_init<<<(NU + 255) / 256, 256>>>();
    k_node<<<(NT + 63) / 64, 256>>>(fu, fi, W1, b1, out);
    k_attn<<<(NT * 32 + 255) / 256, 256>>>(fu, fi, attn);
    k_logits<<<EE / 256, 256>>>(src, dst);
    k_exp<<<EE / 256, 256>>>(src, dst);
    k_edge<<<EE / 64, 256>>>(fu, fi, src, dst, nui, niu, W2, b2, out);
    k_finish<<<(NT * 32 + 255) / 256, 256>>>(out);
}

// round 2
// speedup vs baseline: 2.3686x; 2.3686x over previous
#include <cuda_runtime.h>
#include <math.h>

#define NU 50000
#define NI 50000
#define DD 128
#define EE 800000
#define NT (NU + NI)

// ---------------- scratch ----------------
__device__ float g_Gu[NU * DD];            // sum_e w2_e * feat_item[dst_e]  (per user)
__device__ float g_Gi[NI * DD];            // sum_e w1_e * feat_user[src_e]  (per item)
__device__ float g_Su[NU], g_Si[NI];       // sum of weights per node
__device__ float g_as_u[NU], g_ad_u[NU];   // feat . attn[:D], feat . attn[D:]
__device__ float g_as_i[NI], g_ad_i[NI];
__device__ float g_ex1[EE], g_ex2[EE];     // logits, then exp(a - max)
__device__ float g_max_u[NU], g_max_i[NI];
__device__ float g_den_u[NU], g_den_i[NI];

__device__ __forceinline__ float leakyf(float x) { return x >= 0.f ? x : 0.2f * x; }

__device__ __forceinline__ void atomicMaxF(float* addr, float v) {
    if (v >= 0.f) atomicMax((int*)addr, __float_as_int(v));
    else          atomicMin((unsigned int*)addr, __float_as_uint(v));
}

__device__ __forceinline__ void red4(float* p, float a, float b, float c, float d) {
    asm volatile("red.global.add.v4.f32 [%0], {%1,%2,%3,%4};"
                 :: "l"(p), "f"(a), "f"(b), "f"(c), "f"(d) : "memory");
}

// ---------------- K0: init scratch ----------------
__global__ void k_init() {
    int i = blockIdx.x * blockDim.x + threadIdx.x;
    int stride = gridDim.x * blockDim.x;
    const int n4 = NU * DD / 4;
    float4 z = make_float4(0.f, 0.f, 0.f, 0.f);
    for (int j = i; j < n4; j += stride) {
        ((float4*)g_Gu)[j] = z;
        ((float4*)g_Gi)[j] = z;
    }
    if (i < NU) {
        g_Su[i] = 0.f; g_Si[i] = 0.f;
        g_max_u[i] = -INFINITY; g_max_i[i] = -INFINITY;
        g_den_u[i] = 0.f; g_den_i[i] = 0.f;
    }
}

// ---------------- K1: self term  h = feat @ W1^T + b1  -> out ----------------
// 64 rows per block, 256 threads; thread = (eg,og) computes 4 rows x 8 outs.
__global__ __launch_bounds__(256) void k_node(const float* __restrict__ fu,
                                              const float* __restrict__ fi,
                                              const float* __restrict__ W1,
                                              const float* __restrict__ b1,
                                              float* __restrict__ out) {
    const int t = threadIdx.x;
    const int eg = t >> 4, og = t & 15;
    const int rowBase = blockIdx.x * 64;

    __shared__ float fs[64][36];
    __shared__ float ws[32][132];
    __shared__ float b1s[128];
    if (t < 128) b1s[t] = b1[t];

    float acc[4][8];
#pragma unroll
    for (int i = 0; i < 4; i++)
#pragma unroll
        for (int j = 0; j < 8; j++) acc[i][j] = 0.f;

    for (int kc = 0; kc < 128; kc += 32) {
        for (int idx = t; idx < 512; idx += 256) {
            int r = idx >> 3, c4 = idx & 7;
            int row = rowBase + r;
            float4 v = make_float4(0.f, 0.f, 0.f, 0.f);
            if (row < NT) {
                const float* f = (row < NU) ? (fu + (size_t)row * DD)
                                            : (fi + (size_t)(row - NU) * DD);
                v = *(const float4*)(f + kc + c4 * 4);
            }
            *(float4*)&fs[r][c4 * 4] = v;
        }
        for (int idx = t; idx < 4096; idx += 256) {
            int o = idx >> 5, k = idx & 31;
            ws[k][o] = W1[o * DD + kc + k];
        }
        __syncthreads();
#pragma unroll
        for (int k = 0; k < 32; k++) {
            float z[4];
#pragma unroll
            for (int i = 0; i < 4; i++) z[i] = fs[eg * 4 + i][k];
            float w[8];
            *(float4*)&w[0] = *(const float4*)&ws[k][og * 8];
            *(float4*)&w[4] = *(const float4*)&ws[k][og * 8 + 4];
#pragma unroll
            for (int i = 0; i < 4; i++)
#pragma unroll
                for (int j = 0; j < 8; j++) acc[i][j] += z[i] * w[j];
        }
        __syncthreads();
    }

#pragma unroll
    for (int i = 0; i < 4; i++) {
        int row = rowBase + eg * 4 + i;
        if (row >= NT) continue;
        float o8[8];
#pragma unroll
        for (int j = 0; j < 8; j++) o8[j] = acc[i][j] + b1s[og * 8 + j];
        float* ho = out + (size_t)row * DD;
        *(float4*)(ho + og * 8)     = *(float4*)&o8[0];
        *(float4*)(ho + og * 8 + 4) = *(float4*)&o8[4];
    }
}

// ---------------- K1b: per-node attention dots ----------------
__global__ __launch_bounds__(256) void k_attn(const float* __restrict__ fu,
                                              const float* __restrict__ fi,
                                              const float* __restrict__ attn) {
    __shared__ float at[256];
    int t = threadIdx.x;
    at[t] = attn[t];
    __syncthreads();
    int gwarp = (blockIdx.x * 256 + t) >> 5;
    int lane = t & 31;
    if (gwarp >= NT) return;
    const float* f = (gwarp < NU) ? (fu + (size_t)gwarp * DD)
                                  : (fi + (size_t)(gwarp - NU) * DD);
    float4 v = *(const float4*)(f + lane * 4);
    float4 a1 = *(const float4*)&at[lane * 4];
    float4 a2 = *(const float4*)&at[128 + lane * 4];
    float s = v.x * a1.x + v.y * a1.y + v.z * a1.z + v.w * a1.w;
    float d = v.x * a2.x + v.y * a2.y + v.z * a2.z + v.w * a2.w;
#pragma unroll
    for (int m = 16; m > 0; m >>= 1) {
        s += __shfl_xor_sync(0xffffffffu, s, m);
        d += __shfl_xor_sync(0xffffffffu, d, m);
    }
    if (lane == 0) {
        if (gwarp < NU) { g_as_u[gwarp] = s; g_ad_u[gwarp] = d; }
        else            { g_as_i[gwarp - NU] = s; g_ad_i[gwarp - NU] = d; }
    }
}

// ---------------- K2: edge logits + segment max ----------------
__global__ void k_logits(const int* __restrict__ src, const int* __restrict__ dst) {
    int e = blockIdx.x * blockDim.x + threadIdx.x;
    if (e >= EE) return;
    int s = src[e], d = dst[e];
    float a1 = leakyf(g_as_u[s] + g_ad_i[d]);   // user->item, segments over item (d)
    float a2 = leakyf(g_as_i[d] + g_ad_u[s]);   // item->user, segments over user (s)
    g_ex1[e] = a1;
    g_ex2[e] = a2;
    atomicMaxF(&g_max_i[d], a1);
    atomicMaxF(&g_max_u[s], a2);
}

// ---------------- K3: exp + segment denom ----------------
__global__ void k_exp(const int* __restrict__ src, const int* __restrict__ dst) {
    int e = blockIdx.x * blockDim.x + threadIdx.x;
    if (e >= EE) return;
    int s = src[e], d = dst[e];
    float e1 = expf(g_ex1[e] - g_max_i[d]);
    float e2 = expf(g_ex2[e] - g_max_u[s]);
    g_ex1[e] = e1;
    g_ex2[e] = e2;
    atomicAdd(&g_den_i[d], e1);
    atomicAdd(&g_den_u[s], e2);
}

// ---------------- K4: edge scatter — weighted feature aggregation ----------------
// One warp per edge: G_i[d] += w1*feat_user[s];  G_u[s] += w2*feat_item[d]
__global__ __launch_bounds__(256) void k_scatter(const float* __restrict__ fu,
                                                 const float* __restrict__ fi,
                                                 const int* __restrict__ src,
                                                 const int* __restrict__ dst,
                                                 const float* __restrict__ nui,
                                                 const float* __restrict__ niu) {
    int e = (blockIdx.x * 256 + threadIdx.x) >> 5;
    int lane = threadIdx.x & 31;
    if (e >= EE) return;
    int s = src[e], d = dst[e];
    float w1 = g_ex1[e] / g_den_i[d] * nui[e];   // alpha1 * norm_ui
    float w2 = g_ex2[e] / g_den_u[s] * niu[e];   // alpha2 * norm_iu
    float4 a = *(const float4*)(fu + (size_t)s * DD + lane * 4);
    float4 b = *(const float4*)(fi + (size_t)d * DD + lane * 4);
    red4(g_Gi + (size_t)d * DD + lane * 4, w1 * a.x, w1 * a.y, w1 * a.z, w1 * a.w);
    red4(g_Gu + (size_t)s * DD + lane * 4, w2 * b.x, w2 * b.y, w2 * b.z, w2 * b.w);
    if (lane == 0) {
        atomicAdd(&g_Si[d], w1);
        atomicAdd(&g_Su[s], w2);
    }
}

// ---------------- K5: node cross term — out += G W1^T + (G∘x) W2^T + S(b1+b2) ----------------
// 64 rows/block, 256 threads, k-chunk 16, dual GEMM per thread (4 rows x 8 outs).
__global__ __launch_bounds__(256) void k_node2(const float* __restrict__ fu,
                                               const float* __restrict__ fi,
                                               const float* __restrict__ W1,
                                               const float* __restrict__ W2,
                                               const float* __restrict__ b1,
                                               const float* __restrict__ b2,
                                               float* __restrict__ out) {
    const int t = threadIdx.x;
    const int eg = t >> 4, og = t & 15;
    const int rowBase = blockIdx.x * 64;

    __shared__ float gs[64][20];    // G chunk
    __shared__ float zs[64][20];    // (G∘x) chunk
    __shared__ float w1c[16][132];
    __shared__ float w2c[16][132];
    __shared__ float bs[128];
    __shared__ float srow[64];

    if (t < 128) bs[t] = b1[t] + b2[t];
    if (t < 64) {
        int row = rowBase + t;
        float sv = 0.f;
        if (row < NT) sv = (row < NU) ? g_Su[row] : g_Si[row - NU];
        srow[t] = sv;
    }

    float acc[4][8];
#pragma unroll
    for (int i = 0; i < 4; i++)
#pragma unroll
        for (int j = 0; j < 8; j++) acc[i][j] = 0.f;

    for (int kc = 0; kc < 128; kc += 16) {
        // stage G and G∘x chunks: 64 rows x 16 floats = 256 float4, 1 per thread
        {
            int r = t >> 2, c4 = t & 3;
            int row = rowBase + r;
            float4 g = make_float4(0.f, 0.f, 0.f, 0.f);
            float4 f = make_float4(0.f, 0.f, 0.f, 0.f);
            if (row < NT) {
                if (row < NU) {
                    g = *(const float4*)(g_Gu + (size_t)row * DD + kc + c4 * 4);
                    f = *(const float4*)(fu + (size_t)row * DD + kc + c4 * 4);
                } else {
                    g = *(const float4*)(g_Gi + (size_t)(row - NU) * DD + kc + c4 * 4);
                    f = *(const float4*)(fi + (size_t)(row - NU) * DD + kc + c4 * 4);
                }
            }
            *(float4*)&gs[r][c4 * 4] = g;
            float4 z;
            z.x = g.x * f.x; z.y = g.y * f.y; z.z = g.z * f.z; z.w = g.w * f.w;
            *(float4*)&zs[r][c4 * 4] = z;
        }
        // stage W1^T / W2^T chunks: 16 x 128 each
        for (int idx = t; idx < 2048; idx += 256) {
            int o = idx >> 4, k = idx & 15;
            w1c[k][o] = W1[o * DD + kc + k];
            w2c[k][o] = W2[o * DD + kc + k];
        }
        __syncthreads();
#pragma unroll
        for (int k = 0; k < 16; k++) {
            float g4[4], z4[4];
#pragma unroll
            for (int i = 0; i < 4; i++) {
                g4[i] = gs[eg * 4 + i][k];
                z4[i] = zs[eg * 4 + i][k];
            }
            float wa[8], wb[8];
            *(float4*)&wa[0] = *(const float4*)&w1c[k][og * 8];
            *(float4*)&wa[4] = *(const float4*)&w1c[k][og * 8 + 4];
            *(float4*)&wb[0] = *(const float4*)&w2c[k][og * 8];
            *(float4*)&wb[4] = *(const float4*)&w2c[k][og * 8 + 4];
#pragma unroll
            for (int i = 0; i < 4; i++)
#pragma unroll
                for (int j = 0; j < 8; j++)
                    acc[i][j] += g4[i] * wa[j] + z4[i] * wb[j];
        }
        __syncthreads();
    }

    const int co = og * 8;
#pragma unroll
    for (int i = 0; i < 4; i++) {
        int row = rowBase + eg * 4 + i;
        if (row >= NT) continue;
        float sv = srow[eg * 4 + i];
        float* ho = out + (size_t)row * DD + co;
        float4 o0 = *(float4*)ho;
        float4 o1 = *(float4*)(ho + 4);
        o0.x += acc[i][0] + sv * bs[co + 0];
        o0.y += acc[i][1] + sv * bs[co + 1];
        o0.z += acc[i][2] + sv * bs[co + 2];
        o0.w += acc[i][3] + sv * bs[co + 3];
        o1.x += acc[i][4] + sv * bs[co + 4];
        o1.y += acc[i][5] + sv * bs[co + 5];
        o1.z += acc[i][6] + sv * bs[co + 6];
        o1.w += acc[i][7] + sv * bs[co + 7];
        *(float4*)ho       = o0;
        *(float4*)(ho + 4) = o1;
    }
}

// ---------------- K6: leaky + L2 normalize (in place on d_out) ----------------
__global__ __launch_bounds__(256) void k_finish(float* __restrict__ out) {
    int gwarp = (blockIdx.x * 256 + threadIdx.x) >> 5;
    int lane = threadIdx.x & 31;
    if (gwarp >= NT) return;
    float* p = out + (size_t)gwarp * DD;
    float4 v = *(float4*)(p + lane * 4);
    v.x = leakyf(v.x); v.y = leakyf(v.y); v.z = leakyf(v.z); v.w = leakyf(v.w);
    float s = v.x * v.x + v.y * v.y + v.z * v.z + v.w * v.w;
#pragma unroll
    for (int m = 16; m > 0; m >>= 1) s += __shfl_xor_sync(0xffffffffu, s, m);
    float n = sqrtf(s);
    float inv = 1.f / fmaxf(n, 1e-12f);
    v.x *= inv; v.y *= inv; v.z *= inv; v.w *= inv;
    *(float4*)(p + lane * 4) = v;
}

// ---------------- launch ----------------
extern "C" void kernel_launch(void* const* d_in, const int* in_sizes, int n_in,
                              void* d_out, int out_size) {
    const float* fu   = (const float*)d_in[0];
    const float* fi   = (const float*)d_in[1];
    const int*   src  = (const int*)d_in[2];
    const int*   dst  = (const int*)d_in[3];
    const float* nui  = (const float*)d_in[4];
    const float* niu  = (const float*)d_in[5];
    const float* W1   = (const float*)d_in[6];
    const float* b1   = (const float*)d_in[7];
    const float* W2   = (const float*)d_in[8];
    const float* b2   = (const float*)d_in[9];
    const float* attn = (const float*)d_in[10];
    float* out = (float*)d_out;

    k_init<<<6400, 256>>>();
    k_node<<<(NT + 63) / 64, 256>>>(fu, fi, W1, b1, out);
    k_attn<<<(NT * 32 + 255) / 256, 256>>>(fu, fi, attn);
    k_logits<<<EE / 256, 256>>>(src, dst);
    k_exp<<<EE / 256, 256>>>(src, dst);
    k_scatter<<<EE / 8, 256>>>(fu, fi, src, dst, nui, niu);
    k_node2<<<(NT + 63) / 64, 256>>>(fu, fi, W1, W2, b1, b2, out);
    k_finish<<<(NT * 32 + 255) / 256, 256>>>(out);
}

// round 3
// speedup vs baseline: 3.5821x; 1.5123x over previous
#include <cuda_runtime.h>
#include <math.h>

#define NU 50000
#define NI 50000
#define DD 128
#define EE 800000
#define NT (NU + NI)

// ---------------- scratch ----------------
__device__ float g_Gu[NU * DD];            // sum_e w2_e * feat_item[dst_e]  (per user)
__device__ float g_Gi[NI * DD];            // sum_e w1_e * feat_user[src_e]  (per item)
__device__ float g_Su[NU], g_Si[NI];       // sum of weights per node
__device__ float g_as_u[NU], g_ad_u[NU];   // feat . attn[:D], feat . attn[D:]
__device__ float g_as_i[NI], g_ad_i[NI];
__device__ float g_ex1[EE], g_ex2[EE];     // exp(logit)
__device__ float g_den_u[NU], g_den_i[NI];

__device__ __forceinline__ float leakyf(float x) { return x >= 0.f ? x : 0.2f * x; }

__device__ __forceinline__ void red4(float* p, float a, float b, float c, float d) {
    asm volatile("red.global.add.v4.f32 [%0], {%1,%2,%3,%4};"
                 :: "l"(p), "f"(a), "f"(b), "f"(c), "f"(d) : "memory");
}

// ---------------- K0: init scratch ----------------
__global__ void k_init() {
    int i = blockIdx.x * blockDim.x + threadIdx.x;
    int stride = gridDim.x * blockDim.x;
    const int n4 = NU * DD / 4;
    float4 z = make_float4(0.f, 0.f, 0.f, 0.f);
    for (int j = i; j < n4; j += stride) {
        ((float4*)g_Gu)[j] = z;
        ((float4*)g_Gi)[j] = z;
    }
    if (i < NU) {
        g_Su[i] = 0.f; g_Si[i] = 0.f;
        g_den_u[i] = 0.f; g_den_i[i] = 0.f;
    }
}

// ---------------- K1: per-node attention dots ----------------
__global__ __launch_bounds__(256) void k_attn(const float* __restrict__ fu,
                                              const float* __restrict__ fi,
                                              const float* __restrict__ attn) {
    __shared__ float at[256];
    int t = threadIdx.x;
    at[t] = attn[t];
    __syncthreads();
    int gwarp = (blockIdx.x * 256 + t) >> 5;
    int lane = t & 31;
    if (gwarp >= NT) return;
    const float* f = (gwarp < NU) ? (fu + (size_t)gwarp * DD)
                                  : (fi + (size_t)(gwarp - NU) * DD);
    float4 v = *(const float4*)(f + lane * 4);
    float4 a1 = *(const float4*)&at[lane * 4];
    float4 a2 = *(const float4*)&at[128 + lane * 4];
    float s = v.x * a1.x + v.y * a1.y + v.z * a1.z + v.w * a1.w;
    float d = v.x * a2.x + v.y * a2.y + v.z * a2.z + v.w * a2.w;
#pragma unroll
    for (int m = 16; m > 0; m >>= 1) {
        s += __shfl_xor_sync(0xffffffffu, s, m);
        d += __shfl_xor_sync(0xffffffffu, d, m);
    }
    if (lane == 0) {
        if (gwarp < NU) { g_as_u[gwarp] = s; g_ad_u[gwarp] = d; }
        else            { g_as_i[gwarp - NU] = s; g_ad_i[gwarp - NU] = d; }
    }
}

// ---------------- K2: softmax numerators + denominators (no max pass: shift-invariant,
// logits = leaky(dot) are O(±8) so exp() is safe) ----------------
__global__ void k_softmax(const int* __restrict__ src, const int* __restrict__ dst) {
    int e = blockIdx.x * blockDim.x + threadIdx.x;
    if (e >= EE) return;
    int s = src[e], d = dst[e];
    float e1 = __expf(leakyf(g_as_u[s] + g_ad_i[d]));  // user->item, segments over item d
    float e2 = __expf(leakyf(g_as_i[d] + g_ad_u[s]));  // item->user, segments over user s
    g_ex1[e] = e1;
    g_ex2[e] = e2;
    atomicAdd(&g_den_i[d], e1);
    atomicAdd(&g_den_u[s], e2);
}

// ---------------- K3: edge scatter — weighted feature aggregation ----------------
// One warp per edge: G_i[d] += w1*feat_user[s];  G_u[s] += w2*feat_item[d]
__global__ __launch_bounds__(256) void k_scatter(const float* __restrict__ fu,
                                                 const float* __restrict__ fi,
                                                 const int* __restrict__ src,
                                                 const int* __restrict__ dst,
                                                 const float* __restrict__ nui,
                                                 const float* __restrict__ niu) {
    int e = (blockIdx.x * 256 + threadIdx.x) >> 5;
    int lane = threadIdx.x & 31;
    if (e >= EE) return;
    int s = src[e], d = dst[e];
    float w1 = g_ex1[e] / g_den_i[d] * nui[e];   // alpha1 * norm_ui
    float w2 = g_ex2[e] / g_den_u[s] * niu[e];   // alpha2 * norm_iu
    float4 a = *(const float4*)(fu + (size_t)s * DD + lane * 4);
    float4 b = *(const float4*)(fi + (size_t)d * DD + lane * 4);
    red4(g_Gi + (size_t)d * DD + lane * 4, w1 * a.x, w1 * a.y, w1 * a.z, w1 * a.w);
    red4(g_Gu + (size_t)s * DD + lane * 4, w2 * b.x, w2 * b.y, w2 * b.z, w2 * b.w);
    if (lane == 0) {
        atomicAdd(&g_Si[d], w1);
        atomicAdd(&g_Su[s], w2);
    }
}

// ---------------- K4: fused dense — h = (feat+G)W1^T + (G∘feat)W2^T + b1 + S(b1+b2),
// then leaky + L2 normalize, write d_out. 128 rows/block, 256 threads, 8x8 tiles.
__global__ __launch_bounds__(256) void k_fused(const float* __restrict__ fu,
                                               const float* __restrict__ fi,
                                               const float* __restrict__ W1,
                                               const float* __restrict__ W2,
                                               const float* __restrict__ b1,
                                               const float* __restrict__ b2,
                                               float* __restrict__ out) {
    const int t = threadIdx.x;
    const int eg = t >> 4, og = t & 15;     // eg: 8-row group, og: 8-col group
    const int rowBase = blockIdx.x * 128;

    __shared__ float As[128][20];   // feat + G   (k-chunk of 16, padded)
    __shared__ float Zs[128][20];   // G ∘ feat
    __shared__ float w1c[16][132];
    __shared__ float w2c[16][132];
    __shared__ float b1s[128], bsum[128], srow[128];
    __shared__ float sq[128][17];

    if (t < 128) {
        b1s[t] = b1[t];
        bsum[t] = b1[t] + b2[t];
        int row = rowBase + t;
        float sv = 0.f;
        if (row < NT) sv = (row < NU) ? g_Su[row] : g_Si[row - NU];
        srow[t] = sv;
    }

    float acc[8][8];
#pragma unroll
    for (int i = 0; i < 8; i++)
#pragma unroll
        for (int j = 0; j < 8; j++) acc[i][j] = 0.f;

    for (int kc = 0; kc < 128; kc += 16) {
        // stage A and Z chunks: 128 rows x 16 floats = 512 float4, 2 per thread
        for (int idx = t; idx < 512; idx += 256) {
            int r = idx >> 2, c4 = idx & 3;
            int row = rowBase + r;
            float4 g = make_float4(0.f, 0.f, 0.f, 0.f);
            float4 f = make_float4(0.f, 0.f, 0.f, 0.f);
            if (row < NT) {
                if (row < NU) {
                    g = *(const float4*)(g_Gu + (size_t)row * DD + kc + c4 * 4);
                    f = *(const float4*)(fu + (size_t)row * DD + kc + c4 * 4);
                } else {
                    g = *(const float4*)(g_Gi + (size_t)(row - NU) * DD + kc + c4 * 4);
                    f = *(const float4*)(fi + (size_t)(row - NU) * DD + kc + c4 * 4);
                }
            }
            float4 a, z;
            a.x = f.x + g.x; a.y = f.y + g.y; a.z = f.z + g.z; a.w = f.w + g.w;
            z.x = g.x * f.x; z.y = g.y * f.y; z.z = g.z * f.z; z.w = g.w * f.w;
            *(float4*)&As[r][c4 * 4] = a;
            *(float4*)&Zs[r][c4 * 4] = z;
        }
        // stage W1^T / W2^T chunks: 16 x 128 each
        for (int idx = t; idx < 2048; idx += 256) {
            int o = idx >> 4, k = idx & 15;
            w1c[k][o] = W1[o * DD + kc + k];
            w2c[k][o] = W2[o * DD + kc + k];
        }
        __syncthreads();
#pragma unroll
        for (int k = 0; k < 16; k++) {
            float a8[8];
#pragma unroll
            for (int i = 0; i < 8; i++) a8[i] = As[eg * 8 + i][k];
            float w[8];
            *(float4*)&w[0] = *(const float4*)&w1c[k][og * 8];
            *(float4*)&w[4] = *(const float4*)&w1c[k][og * 8 + 4];
#pragma unroll
            for (int i = 0; i < 8; i++)
#pragma unroll
                for (int j = 0; j < 8; j++) acc[i][j] += a8[i] * w[j];
            float z8[8];
#pragma unroll
            for (int i = 0; i < 8; i++) z8[i] = Zs[eg * 8 + i][k];
            *(float4*)&w[0] = *(const float4*)&w2c[k][og * 8];
            *(float4*)&w[4] = *(const float4*)&w2c[k][og * 8 + 4];
#pragma unroll
            for (int i = 0; i < 8; i++)
#pragma unroll
                for (int j = 0; j < 8; j++) acc[i][j] += z8[i] * w[j];
        }
        __syncthreads();
    }

    // epilogue: bias, leaky, row-sumsq
    const int co = og * 8;
#pragma unroll
    for (int i = 0; i < 8; i++) {
        int r = eg * 8 + i;
        float sv = srow[r];
        float ssq = 0.f;
#pragma unroll
        for (int j = 0; j < 8; j++) {
            float v = leakyf(acc[i][j] + b1s[co + j] + sv * bsum[co + j]);
            acc[i][j] = v;
            ssq += v * v;
        }
        sq[r][og] = ssq;
    }
    __syncthreads();
#pragma unroll
    for (int i = 0; i < 8; i++) {
        int r = eg * 8 + i;
        int row = rowBase + r;
        if (row >= NT) continue;
        float s = 0.f;
#pragma unroll
        for (int o = 0; o < 16; o++) s += sq[r][o];
        float inv = 1.f / fmaxf(sqrtf(s), 1e-12f);
        float o8[8];
#pragma unroll
        for (int j = 0; j < 8; j++) o8[j] = acc[i][j] * inv;
        float* ho = out + (size_t)row * DD + co;
        *(float4*)ho       = *(float4*)&o8[0];
        *(float4*)(ho + 4) = *(float4*)&o8[4];
    }
}

// ---------------- launch ----------------
extern "C" void kernel_launch(void* const* d_in, const int* in_sizes, int n_in,
                              void* d_out, int out_size) {
    const float* fu   = (const float*)d_in[0];
    const float* fi   = (const float*)d_in[1];
    const int*   src  = (const int*)d_in[2];
    const int*   dst  = (const int*)d_in[3];
    const float* nui  = (const float*)d_in[4];
    const float* niu  = (const float*)d_in[5];
    const float* W1   = (const float*)d_in[6];
    const float* b1   = (const float*)d_in[7];
    const float* W2   = (const float*)d_in[8];
    const float* b2   = (const float*)d_in[9];
    const float* attn = (const float*)d_in[10];
    float* out = (float*)d_out;

    k_init<<<6400, 256>>>();
    k_attn<<<(NT * 32 + 255) / 256, 256>>>(fu, fi, attn);
    k_softmax<<<EE / 256, 256>>>(src, dst);
    k_scatter<<<EE / 8, 256>>>(fu, fi, src, dst, nui, niu);
    k_fused<<<(NT + 127) / 128, 256>>>(fu, fi, W1, W2, b1, b2, out);
}

// round 4
// speedup vs baseline: 3.8294x; 1.0690x over previous
#include <cuda_runtime.h>
#include <math.h>

#define NU 50000
#define NI 50000
#define DD 128
#define EE 800000
#define NT (NU + NI)

typedef unsigned long long u64;

// ---------------- scratch ----------------
__device__ float g_Gu[NU * DD];            // sum_e w2_e * feat_item[dst_e]  (per user)
__device__ float g_Gi[NI * DD];            // sum_e w1_e * feat_user[src_e]  (per item)
__device__ float g_Su[NU], g_Si[NI];       // sum of weights per node
__device__ float g_as_u[NU], g_ad_u[NU];   // feat . attn[:D], feat . attn[D:]
__device__ float g_as_i[NI], g_ad_i[NI];
__device__ float g_ex1[EE], g_ex2[EE];     // exp(logit)
__device__ float g_den_u[NU], g_den_i[NI];

__device__ __forceinline__ float leakyf(float x) { return x >= 0.f ? x : 0.2f * x; }

__device__ __forceinline__ void red4(float* p, float a, float b, float c, float d) {
    asm volatile("red.global.add.v4.f32 [%0], {%1,%2,%3,%4};"
                 :: "l"(p), "f"(a), "f"(b), "f"(c), "f"(d) : "memory");
}

__device__ __forceinline__ u64 pk2(float x) {
    u64 r; asm("mov.b64 %0, {%1, %1};" : "=l"(r) : "f"(x)); return r;
}
#define FFMA2(d, a, b) asm("fma.rn.f32x2 %0, %1, %2, %0;" : "+l"(d) : "l"(a), "l"(b))

// ---------------- K0: init scratch ----------------
__global__ void k_init() {
    int i = blockIdx.x * blockDim.x + threadIdx.x;
    int stride = gridDim.x * blockDim.x;
    const int n4 = NU * DD / 4;
    float4 z = make_float4(0.f, 0.f, 0.f, 0.f);
    for (int j = i; j < n4; j += stride) {
        ((float4*)g_Gu)[j] = z;
        ((float4*)g_Gi)[j] = z;
    }
    if (i < NU) {
        g_Su[i] = 0.f; g_Si[i] = 0.f;
        g_den_u[i] = 0.f; g_den_i[i] = 0.f;
    }
}

// ---------------- K1: per-node attention dots ----------------
__global__ __launch_bounds__(256) void k_attn(const float* __restrict__ fu,
                                              const float* __restrict__ fi,
                                              const float* __restrict__ attn) {
    __shared__ float at[256];
    int t = threadIdx.x;
    at[t] = attn[t];
    __syncthreads();
    int gwarp = (blockIdx.x * 256 + t) >> 5;
    int lane = t & 31;
    if (gwarp >= NT) return;
    const float* f = (gwarp < NU) ? (fu + (size_t)gwarp * DD)
                                  : (fi + (size_t)(gwarp - NU) * DD);
    float4 v = *(const float4*)(f + lane * 4);
    float4 a1 = *(const float4*)&at[lane * 4];
    float4 a2 = *(const float4*)&at[128 + lane * 4];
    float s = v.x * a1.x + v.y * a1.y + v.z * a1.z + v.w * a1.w;
    float d = v.x * a2.x + v.y * a2.y + v.z * a2.z + v.w * a2.w;
#pragma unroll
    for (int m = 16; m > 0; m >>= 1) {
        s += __shfl_xor_sync(0xffffffffu, s, m);
        d += __shfl_xor_sync(0xffffffffu, d, m);
    }
    if (lane == 0) {
        if (gwarp < NU) { g_as_u[gwarp] = s; g_ad_u[gwarp] = d; }
        else            { g_as_i[gwarp - NU] = s; g_ad_i[gwarp - NU] = d; }
    }
}

// ---------------- K2: softmax numerators + denominators (no max pass: shift-invariant,
// logits = leaky(dot) are O(±8) so exp() is safe) ----------------
__global__ void k_softmax(const int* __restrict__ src, const int* __restrict__ dst) {
    int e = blockIdx.x * blockDim.x + threadIdx.x;
    if (e >= EE) return;
    int s = src[e], d = dst[e];
    float e1 = __expf(leakyf(g_as_u[s] + g_ad_i[d]));  // user->item, segments over item d
    float e2 = __expf(leakyf(g_as_i[d] + g_ad_u[s]));  // item->user, segments over user s
    g_ex1[e] = e1;
    g_ex2[e] = e2;
    atomicAdd(&g_den_i[d], e1);
    atomicAdd(&g_den_u[s], e2);
}

// ---------------- K3: edge scatter — 4 edges per warp, phase-batched for MLP ----------------
__global__ __launch_bounds__(256) void k_scatter(const float* __restrict__ fu,
                                                 const float* __restrict__ fi,
                                                 const int* __restrict__ src,
                                                 const int* __restrict__ dst,
                                                 const float* __restrict__ nui,
                                                 const float* __restrict__ niu) {
    int w = (blockIdx.x * 256 + threadIdx.x) >> 5;
    int lane = threadIdx.x & 31;
    int e0 = w * 4;
    if (e0 >= EE) return;

    int s[4], d[4];
#pragma unroll
    for (int j = 0; j < 4; j++) { s[j] = src[e0 + j]; d[j] = dst[e0 + j]; }

    float4 a[4], b[4];
#pragma unroll
    for (int j = 0; j < 4; j++) {
        a[j] = *(const float4*)(fu + (size_t)s[j] * DD + lane * 4);
        b[j] = *(const float4*)(fi + (size_t)d[j] * DD + lane * 4);
    }

    float w1[4], w2[4];
#pragma unroll
    for (int j = 0; j < 4; j++) {
        w1[j] = __fdividef(g_ex1[e0 + j], g_den_i[d[j]]) * nui[e0 + j];
        w2[j] = __fdividef(g_ex2[e0 + j], g_den_u[s[j]]) * niu[e0 + j];
    }

#pragma unroll
    for (int j = 0; j < 4; j++) {
        red4(g_Gi + (size_t)d[j] * DD + lane * 4,
             w1[j] * a[j].x, w1[j] * a[j].y, w1[j] * a[j].z, w1[j] * a[j].w);
        red4(g_Gu + (size_t)s[j] * DD + lane * 4,
             w2[j] * b[j].x, w2[j] * b[j].y, w2[j] * b[j].z, w2[j] * b[j].w);
    }
    if (lane == 0) {
#pragma unroll
        for (int j = 0; j < 4; j++) {
            atomicAdd(&g_Si[d[j]], w1[j]);
            atomicAdd(&g_Su[s[j]], w2[j]);
        }
    }
}

// ---------------- K4: fused dense (FFMA2) — h = (feat+G)W1^T + (G∘feat)W2^T + b1 + S(b1+b2),
// then leaky + L2 normalize, write d_out. 128 rows/block, 256 threads, 8x8 tiles.
__global__ __launch_bounds__(256) void k_fused(const float* __restrict__ fu,
                                               const float* __restrict__ fi,
                                               const float* __restrict__ W1,
                                               const float* __restrict__ W2,
                                               const float* __restrict__ b1,
                                               const float* __restrict__ b2,
                                               float* __restrict__ out) {
    const int t = threadIdx.x;
    const int eg = t >> 4, og = t & 15;     // eg: 8-row group, og: 8-col group
    const int rowBase = blockIdx.x * 128;

    __shared__ float As[128][20];   // feat + G   (k-chunk of 16, padded)
    __shared__ float Zs[128][20];   // G ∘ feat
    __shared__ float w1c[16][132];
    __shared__ float w2c[16][132];
    __shared__ float b1s[128], bsum[128], srow[128];
    __shared__ float sq[128][17];

    if (t < 128) {
        b1s[t] = b1[t];
        bsum[t] = b1[t] + b2[t];
        int row = rowBase + t;
        float sv = 0.f;
        if (row < NT) sv = (row < NU) ? g_Su[row] : g_Si[row - NU];
        srow[t] = sv;
    }

    u64 acc[8][4];
#pragma unroll
    for (int i = 0; i < 8; i++)
#pragma unroll
        for (int j = 0; j < 4; j++) acc[i][j] = 0ull;

    for (int kc = 0; kc < 128; kc += 16) {
        // stage A and Z chunks: 128 rows x 16 floats = 512 float4, 2 per thread
        for (int idx = t; idx < 512; idx += 256) {
            int r = idx >> 2, c4 = idx & 3;
            int row = rowBase + r;
            float4 g = make_float4(0.f, 0.f, 0.f, 0.f);
            float4 f = make_float4(0.f, 0.f, 0.f, 0.f);
            if (row < NT) {
                if (row < NU) {
                    g = *(const float4*)(g_Gu + (size_t)row * DD + kc + c4 * 4);
                    f = *(const float4*)(fu + (size_t)row * DD + kc + c4 * 4);
                } else {
                    g = *(const float4*)(g_Gi + (size_t)(row - NU) * DD + kc + c4 * 4);
                    f = *(const float4*)(fi + (size_t)(row - NU) * DD + kc + c4 * 4);
                }
            }
            float4 aa, zz;
            aa.x = f.x + g.x; aa.y = f.y + g.y; aa.z = f.z + g.z; aa.w = f.w + g.w;
            zz.x = g.x * f.x; zz.y = g.y * f.y; zz.z = g.z * f.z; zz.w = g.w * f.w;
            *(float4*)&As[r][c4 * 4] = aa;
            *(float4*)&Zs[r][c4 * 4] = zz;
        }
        // stage W1^T / W2^T chunks: 16 x 128 each
        for (int idx = t; idx < 2048; idx += 256) {
            int o = idx >> 4, k = idx & 15;
            w1c[k][o] = W1[o * DD + kc + k];
            w2c[k][o] = W2[o * DD + kc + k];
        }
        __syncthreads();
#pragma unroll
        for (int k = 0; k < 16; k++) {
            // W pairs straight from smem as b64 pairs (j-adjacent)
            ulonglong2 p0 = *(const ulonglong2*)&w1c[k][og * 8];
            ulonglong2 p1 = *(const ulonglong2*)&w1c[k][og * 8 + 4];
            ulonglong2 q0 = *(const ulonglong2*)&w2c[k][og * 8];
            ulonglong2 q1 = *(const ulonglong2*)&w2c[k][og * 8 + 4];
            u64 wp[4] = {p0.x, p0.y, p1.x, p1.y};
            u64 vp[4] = {q0.x, q0.y, q1.x, q1.y};
#pragma unroll
            for (int i = 0; i < 8; i++) {
                u64 a2 = pk2(As[eg * 8 + i][k]);
                u64 z2 = pk2(Zs[eg * 8 + i][k]);
                FFMA2(acc[i][0], a2, wp[0]);
                FFMA2(acc[i][1], a2, wp[1]);
                FFMA2(acc[i][2], a2, wp[2]);
                FFMA2(acc[i][3], a2, wp[3]);
                FFMA2(acc[i][0], z2, vp[0]);
                FFMA2(acc[i][1], z2, vp[1]);
                FFMA2(acc[i][2], z2, vp[2]);
                FFMA2(acc[i][3], z2, vp[3]);
            }
        }
        __syncthreads();
    }

    // epilogue: bias, leaky, row-sumsq, normalize
    const int co = og * 8;
    float vals[8];
#pragma unroll
    for (int i = 0; i < 8; i++) {
        int r = eg * 8 + i;
        float sv = srow[r];
        float ssq = 0.f;
#pragma unroll
        for (int jp = 0; jp < 4; jp++) {
            float lo, hi;
            asm("mov.b64 {%0, %1}, %2;" : "=f"(lo), "=f"(hi) : "l"(acc[i][jp]));
            float v0 = leakyf(lo + b1s[co + 2 * jp]     + sv * bsum[co + 2 * jp]);
            float v1 = leakyf(hi + b1s[co + 2 * jp + 1] + sv * bsum[co + 2 * jp + 1]);
            vals[2 * jp] = v0; vals[2 * jp + 1] = v1;
            ssq += v0 * v0 + v1 * v1;
        }
        sq[r][og] = ssq;
        // stash back packed for after-sync store
        acc[i][0] = pk2(0.f);  // placeholder to keep regs alive? (not needed)
#pragma unroll
        for (int jp = 0; jp < 4; jp++) {
            u64 rpk; asm("mov.b64 %0, {%1, %2};" : "=l"(rpk) : "f"(vals[2 * jp]), "f"(vals[2 * jp + 1]));
            acc[i][jp] = rpk;
        }
    }
    __syncthreads();
#pragma unroll
    for (int i = 0; i < 8; i++) {
        int r = eg * 8 + i;
        int row = rowBase + r;
        if (row >= NT) continue;
        float s = 0.f;
#pragma unroll
        for (int o = 0; o < 16; o++) s += sq[r][o];
        float inv = 1.f / fmaxf(sqrtf(s), 1e-12f);
        float o8[8];
#pragma unroll
        for (int jp = 0; jp < 4; jp++) {
            float lo, hi;
            asm("mov.b64 {%0, %1}, %2;" : "=f"(lo), "=f"(hi) : "l"(acc[i][jp]));
            o8[2 * jp] = lo * inv; o8[2 * jp + 1] = hi * inv;
        }
        float* ho = out + (size_t)row * DD + co;
        *(float4*)ho       = *(float4*)&o8[0];
        *(float4*)(ho + 4) = *(float4*)&o8[4];
    }
}

// ---------------- launch ----------------
extern "C" void kernel_launch(void* const* d_in, const int* in_sizes, int n_in,
                              void* d_out, int out_size) {
    const float* fu   = (const float*)d_in[0];
    const float* fi   = (const float*)d_in[1];
    const int*   src  = (const int*)d_in[2];
    const int*   dst  = (const int*)d_in[3];
    const float* nui  = (const float*)d_in[4];
    const float* niu  = (const float*)d_in[5];
    const float* W1   = (const float*)d_in[6];
    const float* b1   = (const float*)d_in[7];
    const float* W2   = (const float*)d_in[8];
    const float* b2   = (const float*)d_in[9];
    const float* attn = (const float*)d_in[10];
    float* out = (float*)d_out;

    k_init<<<6400, 256>>>();
    k_attn<<<(NT * 32 + 255) / 256, 256>>>(fu, fi, attn);
    k_softmax<<<EE / 256, 256>>>(src, dst);
    k_scatter<<<(EE / 4 + 7) / 8, 256>>>(fu, fi, src, dst, nui, niu);
    k_fused<<<(NT + 127) / 128, 256>>>(fu, fi, W1, W2, b1, b2, out);
}

// round 7
// speedup vs baseline: 4.1449x; 1.0824x over previous
#include <cuda_runtime.h>
#include <math.h>

#define NU 50000
#define NI 50000
#define DD 128
#define EE 800000
#define NT (NU + NI)

// ---------------- scratch ----------------
__device__ int   g_cnt_i[NI], g_cnt_u[NU];
__device__ int   g_base_i[NI + 1], g_base_u[NU + 1];
__device__ int   g_cur_i[NI], g_cur_u[NU];
__device__ int2  g_pair_i[EE], g_pair_u[EE];   // (src, nui) sorted by dst / (dst, niu) sorted by src
__device__ float g_Gu[NU * DD], g_Gi[NI * DD]; // aggregated (already alpha-normalized) features
__device__ float g_Su[NU], g_Si[NI];           // sum of weights per node
__device__ float g_as_u[NU], g_ad_u[NU];       // feat . attn[:D], feat . attn[D:]
__device__ float g_as_i[NI], g_ad_i[NI];
__device__ float g_W1t[DD * DD], g_W2t[DD * DD]; // k-major transposed weights

__device__ __forceinline__ float leakyf(float x) { return x >= 0.f ? x : 0.2f * x; }

// ---------------- K0: zero counters ----------------
__global__ void k_zero() {
    int i = blockIdx.x * blockDim.x + threadIdx.x;
    if (i < NU) { g_cnt_i[i] = 0; g_cnt_u[i] = 0; }
}

// ---------------- K1: degree histograms ----------------
__global__ void k_count(const int* __restrict__ src, const int* __restrict__ dst) {
    int e = blockIdx.x * blockDim.x + threadIdx.x;
    if (e >= EE) return;
    atomicAdd(&g_cnt_i[dst[e]], 1);
    atomicAdd(&g_cnt_u[src[e]], 1);
}

// ---------------- K2: exclusive scan (2 blocks: 0=item, 1=user) ----------------
__global__ __launch_bounds__(1024) void k_scan() {
    const int N = NU;               // == NI
    int* cnt  = blockIdx.x ? g_cnt_u  : g_cnt_i;
    int* base = blockIdx.x ? g_base_u : g_base_i;
    int* cur  = blockIdx.x ? g_cur_u  : g_cur_i;
    __shared__ int part[1024];
    int t = threadIdx.x;
    const int C = (N + 1023) / 1024;
    int lo = t * C, hi = min(lo + C, N);
    int s = 0;
    for (int i = lo; i < hi; i++) s += cnt[i];
    part[t] = s;
    __syncthreads();
    for (int off = 1; off < 1024; off <<= 1) {
        int add = (t >= off) ? part[t - off] : 0;
        __syncthreads();
        part[t] += add;
        __syncthreads();
    }
    int run = (t == 0) ? 0 : part[t - 1];
    for (int i = lo; i < hi; i++) {
        int c = cnt[i];
        base[i] = run; cur[i] = run;
        run += c;
    }
    if (t == 1023) base[N] = run;
}

// ---------------- K3: per-node attention dots ----------------
__global__ __launch_bounds__(256) void k_attn(const float* __restrict__ fu,
                                              const float* __restrict__ fi,
                                              const float* __restrict__ attn) {
    __shared__ float at[256];
    int t = threadIdx.x;
    at[t] = attn[t];
    __syncthreads();
    int gwarp = (blockIdx.x * 256 + t) >> 5;
    int lane = t & 31;
    if (gwarp >= NT) return;
    const float* f = (gwarp < NU) ? (fu + (size_t)gwarp * DD)
                                  : (fi + (size_t)(gwarp - NU) * DD);
    float4 v = *(const float4*)(f + lane * 4);
    float4 a1 = *(const float4*)&at[lane * 4];
    float4 a2 = *(const float4*)&at[128 + lane * 4];
    float s = v.x * a1.x + v.y * a1.y + v.z * a1.z + v.w * a1.w;
    float d = v.x * a2.x + v.y * a2.y + v.z * a2.z + v.w * a2.w;
#pragma unroll
    for (int m = 16; m > 0; m >>= 1) {
        s += __shfl_xor_sync(0xffffffffu, s, m);
        d += __shfl_xor_sync(0xffffffffu, d, m);
    }
    if (lane == 0) {
        if (gwarp < NU) { g_as_u[gwarp] = s; g_ad_u[gwarp] = d; }
        else            { g_as_i[gwarp - NU] = s; g_ad_i[gwarp - NU] = d; }
    }
}

// ---------------- K4: transpose weights to k-major ----------------
__global__ void k_prep(const float* __restrict__ W1, const float* __restrict__ W2) {
    int idx = blockIdx.x * 256 + threadIdx.x;
    if (idx >= DD * DD) return;
    int k = idx >> 7, o = idx & 127;
    g_W1t[idx] = W1[o * DD + k];
    g_W2t[idx] = W2[o * DD + k];
}

// ---------------- K5: permute edges into CSR pair lists ----------------
__global__ void k_permute(const int* __restrict__ src, const int* __restrict__ dst,
                          const float* __restrict__ nui, const float* __restrict__ niu) {
    int e = blockIdx.x * blockDim.x + threadIdx.x;
    if (e >= EE) return;
    int s = src[e], d = dst[e];
    int pi = atomicAdd(&g_cur_i[d], 1);
    g_pair_i[pi] = make_int2(s, __float_as_int(nui[e]));
    int pu = atomicAdd(&g_cur_u[s], 1);
    g_pair_u[pu] = make_int2(d, __float_as_int(niu[e]));
}

// ---------------- K6: gather — per-node register aggregation (softmax fused) ----------------
// warp w < NI: item node (gathers feat_user rows); else user node (gathers feat_item rows).
__global__ __launch_bounds__(256) void k_gather(const float* __restrict__ fu,
                                                const float* __restrict__ fi) {
    int w = (blockIdx.x * 256 + threadIdx.x) >> 5;
    int lane = threadIdx.x & 31;
    if (w >= NT) return;
    bool item = (w < NI);
    int n = item ? w : (w - NI);
    int beg = item ? g_base_i[n] : g_base_u[n];
    int end = item ? g_base_i[n + 1] : g_base_u[n + 1];
    const int2* __restrict__ pairs = item ? g_pair_i : g_pair_u;
    const float* __restrict__ as_arr = item ? g_as_u : g_as_i;
    const float* __restrict__ feat   = item ? fu : fi;
    float adv = item ? g_ad_i[n] : g_ad_u[n];

    float4 acc = make_float4(0.f, 0.f, 0.f, 0.f);
    float aden = 0.f, aS = 0.f;

    int e = beg;
    int2 pr = (e < end) ? pairs[e] : make_int2(0, 0);
    while (e < end) {
        int s = pr.x;
        float nrm = __int_as_float(pr.y);
        int2 prn = make_int2(0, 0);
        if (e + 1 < end) prn = pairs[e + 1];
        float asv = as_arr[s];
        float4 x = *(const float4*)(feat + (size_t)s * DD + lane * 4);
        float ex = __expf(leakyf(asv + adv));
        float wn = ex * nrm;
        acc.x += wn * x.x; acc.y += wn * x.y; acc.z += wn * x.z; acc.w += wn * x.w;
        aden += ex; aS += wn;
        pr = prn; e++;
    }
    float inv = (aden > 0.f) ? __fdividef(1.f, aden) : 0.f;
    float* G = item ? (g_Gi + (size_t)n * DD) : (g_Gu + (size_t)n * DD);
    *(float4*)(G + lane * 4) = make_float4(acc.x * inv, acc.y * inv, acc.z * inv, acc.w * inv);
    if (lane == 0) (item ? g_Si : g_Su)[n] = aS * inv;
}

// ---------------- K7: fused dense (register-prefetch double buffering, no cp.async) ----
// h = (feat+G)W1^T + (G∘feat)W2^T + b1 + S(b1+b2); leaky; L2-normalize; write d_out.
// 128 rows/block, 256 threads, 8x8 per-thread tile, k-chunk 8, 16 chunks.
__global__ __launch_bounds__(256) void k_fused(const float* __restrict__ fu,
                                               const float* __restrict__ fi,
                                               const float* __restrict__ b1,
                                               const float* __restrict__ b2,
                                               float* __restrict__ out) {
    __shared__ float As[2][128][12];   // feat + G   (k-chunk 8, padded to 12)
    __shared__ float Zs[2][128][12];   // G ∘ feat
    __shared__ float w1c[2][8][132];
    __shared__ float w2c[2][8][132];
    __shared__ float b1s[128], bsum[128], srow[128];

    const int t = threadIdx.x;
    const int eg = t >> 4, og = t & 15;
    const int rowBase = blockIdx.x * 128;

    if (t < 128) {
        float v1 = b1[t], v2 = b2[t];
        b1s[t] = v1;
        bsum[t] = v1 + v2;
        int row = rowBase + t;
        float sv = 0.f;
        if (row < NT) sv = (row < NU) ? g_Su[row] : g_Si[row - NU];
        srow[t] = sv;
    }

    // per-thread staging slots
    const int ar = t >> 1, ac4 = (t & 1) * 4;        // A/Z: row, col-offset
    const int wk = t >> 5, wseg = (t & 31) * 4;      // W: k-row, col-offset
    float4 fh, gh;          // held feat/G for next chunk
    float4 w1h, w2h;        // held W rows for next chunk

    auto ldA = [&](int kc) {
        int row = rowBase + ar;
        float4 g = make_float4(0.f, 0.f, 0.f, 0.f);
        float4 f = make_float4(0.f, 0.f, 0.f, 0.f);
        if (row < NT) {
            if (row < NU) {
                g = *(const float4*)(g_Gu + (size_t)row * DD + kc + ac4);
                f = *(const float4*)(fu + (size_t)row * DD + kc + ac4);
            } else {
                g = *(const float4*)(g_Gi + (size_t)(row - NU) * DD + kc + ac4);
                f = *(const float4*)(fi + (size_t)(row - NU) * DD + kc + ac4);
            }
        }
        fh = f; gh = g;
    };
    auto ldW = [&](int kc) {
        w1h = *(const float4*)(g_W1t + (size_t)(kc + wk) * DD + wseg);
        w2h = *(const float4*)(g_W2t + (size_t)(kc + wk) * DD + wseg);
    };
    auto stage = [&](int buf) {
        float4 f = fh, g = gh;
        float4 a, z;
        a.x = f.x + g.x; a.y = f.y + g.y; a.z = f.z + g.z; a.w = f.w + g.w;
        z.x = g.x * f.x; z.y = g.y * f.y; z.z = g.z * f.z; z.w = g.w * f.w;
        *(float4*)&As[buf][ar][ac4] = a;
        *(float4*)&Zs[buf][ar][ac4] = z;
        *(float4*)&w1c[buf][wk][wseg] = w1h;
        *(float4*)&w2c[buf][wk][wseg] = w2h;
    };

    float acc[8][8];
#pragma unroll
    for (int i = 0; i < 8; i++)
#pragma unroll
        for (int j = 0; j < 8; j++) acc[i][j] = 0.f;

    // prologue: chunk 0 staged to buf0; chunk 1 held in regs
    ldA(0); ldW(0); stage(0);
    ldA(8); ldW(8);
    __syncthreads();

    for (int c = 0; c < 16; c++) {
        int cur = c & 1, nb = 1 - cur;
        if (c < 15) {
            stage(nb);                       // write held chunk c+1
            if (c < 14) { ldA((c + 2) * 8); ldW((c + 2) * 8); }   // issue loads for c+2
        }
#pragma unroll
        for (int k = 0; k < 8; k++) {
            float a8[8], z8[8], w[8];
#pragma unroll
            for (int i = 0; i < 8; i++) a8[i] = As[cur][eg * 8 + i][k];
            *(float4*)&w[0] = *(const float4*)&w1c[cur][k][og * 8];
            *(float4*)&w[4] = *(const float4*)&w1c[cur][k][og * 8 + 4];
#pragma unroll
            for (int i = 0; i < 8; i++)
#pragma unroll
                for (int j = 0; j < 8; j++) acc[i][j] += a8[i] * w[j];
#pragma unroll
            for (int i = 0; i < 8; i++) z8[i] = Zs[cur][eg * 8 + i][k];
            *(float4*)&w[0] = *(const float4*)&w2c[cur][k][og * 8];
            *(float4*)&w[4] = *(const float4*)&w2c[cur][k][og * 8 + 4];
#pragma unroll
            for (int i = 0; i < 8; i++)
#pragma unroll
                for (int j = 0; j < 8; j++) acc[i][j] += z8[i] * w[j];
        }
        if (c < 15) __syncthreads();
    }

    // epilogue: bias, leaky, row-sumsq via 16-lane butterfly (og groups are half-warps)
    const int co = og * 8;
#pragma unroll
    for (int i = 0; i < 8; i++) {
        int r = eg * 8 + i;
        int row = rowBase + r;
        float sv = srow[r];
        float ssq = 0.f;
        float vals[8];
#pragma unroll
        for (int j = 0; j < 8; j++) {
            float v = leakyf(acc[i][j] + b1s[co + j] + sv * bsum[co + j]);
            vals[j] = v;
            ssq += v * v;
        }
#pragma unroll
        for (int m = 8; m > 0; m >>= 1)
            ssq += __shfl_xor_sync(0xffffffffu, ssq, m);
        if (row < NT) {
            float inv = 1.f / fmaxf(sqrtf(ssq), 1e-12f);
            float o8[8];
#pragma unroll
            for (int j = 0; j < 8; j++) o8[j] = vals[j] * inv;
            float* ho = out + (size_t)row * DD + co;
            *(float4*)ho       = *(float4*)&o8[0];
            *(float4*)(ho + 4) = *(float4*)&o8[4];
        }
    }
}

// ---------------- launch ----------------
extern "C" void kernel_launch(void* const* d_in, const int* in_sizes, int n_in,
                              void* d_out, int out_size) {
    const float* fu   = (const float*)d_in[0];
    const float* fi   = (const float*)d_in[1];
    const int*   src  = (const int*)d_in[2];
    const int*   dst  = (const int*)d_in[3];
    const float* nui  = (const float*)d_in[4];
    const float* niu  = (const float*)d_in[5];
    const float* W1   = (const float*)d_in[6];
    const float* b1   = (const float*)d_in[7];
    const float* W2   = (const float*)d_in[8];
    const float* b2   = (const float*)d_in[9];
    const float* attn = (const float*)d_in[10];
    float* out = (float*)d_out;

    k_zero<<<(NU + 255) / 256, 256>>>();
    k_count<<<EE / 256, 256>>>(src, dst);
    k_scan<<<2, 1024>>>();
    k_attn<<<(NT * 32 + 255) / 256, 256>>>(fu, fi, attn);
    k_prep<<<(DD * DD + 255) / 256, 256>>>(W1, W2);
    k_permute<<<EE / 256, 256>>>(src, dst, nui, niu);
    k_gather<<<(NT * 32 + 255) / 256, 256>>>(fu, fi);
    k_fused<<<(NT + 127) / 128, 256>>>(fu, fi, b1, b2, out);
}

// round 10
// speedup vs baseline: 4.2051x; 1.0145x over previous
#include <cuda_runtime.h>
#include <math.h>

#define NU 50000
#define NI 50000
#define DD 128
#define EE 800000
#define NT (NU + NI)

typedef unsigned long long u64;

// ---------------- scratch ----------------
__device__ int   g_cnt_i[NI], g_cnt_u[NU];
__device__ int   g_base_i[NI + 1], g_base_u[NU + 1];
__device__ int   g_cur_i[NI], g_cur_u[NU];
__device__ int2  g_pair_i[EE], g_pair_u[EE];   // (src, nui) sorted by dst / (dst, niu) sorted by src
__device__ float g_Gu[NU * DD], g_Gi[NI * DD]; // aggregated (already alpha-normalized) features
__device__ float g_Su[NU], g_Si[NI];           // sum of weights per node
__device__ float g_as_u[NU], g_ad_u[NU];       // feat . attn[:D], feat . attn[D:]
__device__ float g_as_i[NI], g_ad_i[NI];
__device__ float g_W1t[DD * DD], g_W2t[DD * DD]; // k-major transposed weights

__device__ __forceinline__ float leakyf(float x) { return x >= 0.f ? x : 0.2f * x; }

__device__ __forceinline__ u64 pk2(float x) {
    u64 r; asm("mov.b64 %0, {%1, %1};" : "=l"(r) : "f"(x)); return r;
}
__device__ __forceinline__ u64 pk(float lo, float hi) {
    u64 r; asm("mov.b64 %0, {%1, %2};" : "=l"(r) : "f"(lo), "f"(hi)); return r;
}
#define FFMA2(d, a, b) asm("fma.rn.f32x2 %0, %1, %2, %0;" : "+l"(d) : "l"(a), "l"(b))

// ---------------- K0: zero counters ----------------
__global__ void k_zero() {
    int i = blockIdx.x * blockDim.x + threadIdx.x;
    if (i < NU) { g_cnt_i[i] = 0; g_cnt_u[i] = 0; }
}

// ---------------- K1: degree histograms ----------------
__global__ void k_count(const int* __restrict__ src, const int* __restrict__ dst) {
    int e = blockIdx.x * blockDim.x + threadIdx.x;
    if (e >= EE) return;
    atomicAdd(&g_cnt_i[dst[e]], 1);
    atomicAdd(&g_cnt_u[src[e]], 1);
}

// ---------------- K2: exclusive scan (2 blocks: 0=item, 1=user) ----------------
__global__ __launch_bounds__(1024) void k_scan() {
    const int N = NU;               // == NI
    int* cnt  = blockIdx.x ? g_cnt_u  : g_cnt_i;
    int* base = blockIdx.x ? g_base_u : g_base_i;
    int* cur  = blockIdx.x ? g_cur_u  : g_cur_i;
    __shared__ int part[1024];
    int t = threadIdx.x;
    const int C = (N + 1023) / 1024;
    int lo = t * C, hi = min(lo + C, N);
    int s = 0;
    for (int i = lo; i < hi; i++) s += cnt[i];
    part[t] = s;
    __syncthreads();
    for (int off = 1; off < 1024; off <<= 1) {
        int add = (t >= off) ? part[t - off] : 0;
        __syncthreads();
        part[t] += add;
        __syncthreads();
    }
    int run = (t == 0) ? 0 : part[t - 1];
    for (int i = lo; i < hi; i++) {
        int c = cnt[i];
        base[i] = run; cur[i] = run;
        run += c;
    }
    if (t == 1023) base[N] = run;
}

// ---------------- K3: per-node attention dots ----------------
__global__ __launch_bounds__(256) void k_attn(const float* __restrict__ fu,
                                              const float* __restrict__ fi,
                                              const float* __restrict__ attn) {
    __shared__ float at[256];
    int t = threadIdx.x;
    at[t] = attn[t];
    __syncthreads();
    int gwarp = (blockIdx.x * 256 + t) >> 5;
    int lane = t & 31;
    if (gwarp >= NT) return;
    const float* f = (gwarp < NU) ? (fu + (size_t)gwarp * DD)
                                  : (fi + (size_t)(gwarp - NU) * DD);
    float4 v = *(const float4*)(f + lane * 4);
    float4 a1 = *(const float4*)&at[lane * 4];
    float4 a2 = *(const float4*)&at[128 + lane * 4];
    float s = v.x * a1.x + v.y * a1.y + v.z * a1.z + v.w * a1.w;
    float d = v.x * a2.x + v.y * a2.y + v.z * a2.z + v.w * a2.w;
#pragma unroll
    for (int m = 16; m > 0; m >>= 1) {
        s += __shfl_xor_sync(0xffffffffu, s, m);
        d += __shfl_xor_sync(0xffffffffu, d, m);
    }
    if (lane == 0) {
        if (gwarp < NU) { g_as_u[gwarp] = s; g_ad_u[gwarp] = d; }
        else            { g_as_i[gwarp - NU] = s; g_ad_i[gwarp - NU] = d; }
    }
}

// ---------------- K4: transpose weights to k-major ----------------
__global__ void k_prep(const float* __restrict__ W1, const float* __restrict__ W2) {
    int idx = blockIdx.x * 256 + threadIdx.x;
    if (idx >= DD * DD) return;
    int k = idx >> 7, o = idx & 127;
    g_W1t[idx] = W1[o * DD + k];
    g_W2t[idx] = W2[o * DD + k];
}

// ---------------- K5: permute edges into CSR pair lists ----------------
__global__ void k_permute(const int* __restrict__ src, const int* __restrict__ dst,
                          const float* __restrict__ nui, const float* __restrict__ niu) {
    int e = blockIdx.x * blockDim.x + threadIdx.x;
    if (e >= EE) return;
    int s = src[e], d = dst[e];
    int pi = atomicAdd(&g_cur_i[d], 1);
    g_pair_i[pi] = make_int2(s, __float_as_int(nui[e]));
    int pu = atomicAdd(&g_cur_u[s], 1);
    g_pair_u[pu] = make_int2(d, __float_as_int(niu[e]));
}

// ---------------- K6: gather — per-node register aggregation (softmax fused) ----------------
// (exact code that passed at 429.5us)
__global__ __launch_bounds__(256) void k_gather(const float* __restrict__ fu,
                                                const float* __restrict__ fi) {
    int w = (blockIdx.x * 256 + threadIdx.x) >> 5;
    int lane = threadIdx.x & 31;
    if (w >= NT) return;
    bool item = (w < NI);
    int n = item ? w : (w - NI);
    int beg = item ? g_base_i[n] : g_base_u[n];
    int end = item ? g_base_i[n + 1] : g_base_u[n + 1];
    const int2* __restrict__ pairs = item ? g_pair_i : g_pair_u;
    const float* __restrict__ as_arr = item ? g_as_u : g_as_i;
    const float* __restrict__ feat   = item ? fu : fi;
    float adv = item ? g_ad_i[n] : g_ad_u[n];

    float4 acc = make_float4(0.f, 0.f, 0.f, 0.f);
    float aden = 0.f, aS = 0.f;

    int e = beg;
    int2 pr = (e < end) ? pairs[e] : make_int2(0, 0);
    while (e < end) {
        int s = pr.x;
        float nrm = __int_as_float(pr.y);
        int2 prn = make_int2(0, 0);
        if (e + 1 < end) prn = pairs[e + 1];
        float asv = as_arr[s];
        float4 x = *(const float4*)(feat + (size_t)s * DD + lane * 4);
        float ex = __expf(leakyf(asv + adv));
        float wn = ex * nrm;
        acc.x += wn * x.x; acc.y += wn * x.y; acc.z += wn * x.z; acc.w += wn * x.w;
        aden += ex; aS += wn;
        pr = prn; e++;
    }
    float inv = (aden > 0.f) ? __fdividef(1.f, aden) : 0.f;
    float* G = item ? (g_Gi + (size_t)n * DD) : (g_Gu + (size_t)n * DD);
    *(float4*)(G + lane * 4) = make_float4(acc.x * inv, acc.y * inv, acc.z * inv, acc.w * inv);
    if (lane == 0) (item ? g_Si : g_Su)[n] = aS * inv;
}

// ---------------- K7: fused dense (register-prefetch double buffering + f32x2 FMA) ----
// Identical skeleton to the 429.5us pass; only the inner product uses packed FFMA2
// built from proven float4 smem loads + mov.b64 packs (no reinterpret-cast loads).
__global__ __launch_bounds__(256) void k_fused(const float* __restrict__ fu,
                                               const float* __restrict__ fi,
                                               const float* __restrict__ b1,
                                               const float* __restrict__ b2,
                                               float* __restrict__ out) {
    __shared__ float As[2][128][12];   // feat + G   (k-chunk 8, padded to 12)
    __shared__ float Zs[2][128][12];   // G ∘ feat
    __shared__ float w1c[2][8][132];
    __shared__ float w2c[2][8][132];
    __shared__ float b1s[128], bsum[128], srow[128];

    const int t = threadIdx.x;
    const int eg = t >> 4, og = t & 15;
    const int rowBase = blockIdx.x * 128;

    if (t < 128) {
        float v1 = b1[t], v2 = b2[t];
        b1s[t] = v1;
        bsum[t] = v1 + v2;
        int row = rowBase + t;
        float sv = 0.f;
        if (row < NT) sv = (row < NU) ? g_Su[row] : g_Si[row - NU];
        srow[t] = sv;
    }

    // per-thread staging slots
    const int ar = t >> 1, ac4 = (t & 1) * 4;        // A/Z: row, col-offset
    const int wk = t >> 5, wseg = (t & 31) * 4;      // W: k-row, col-offset
    float4 fh, gh;          // held feat/G for next chunk
    float4 w1h, w2h;        // held W rows for next chunk

    auto ldA = [&](int kc) {
        int row = rowBase + ar;
        float4 g = make_float4(0.f, 0.f, 0.f, 0.f);
        float4 f = make_float4(0.f, 0.f, 0.f, 0.f);
        if (row < NT) {
            if (row < NU) {
                g = *(const float4*)(g_Gu + (size_t)row * DD + kc + ac4);
                f = *(const float4*)(fu + (size_t)row * DD + kc + ac4);
            } else {
                g = *(const float4*)(g_Gi + (size_t)(row - NU) * DD + kc + ac4);
                f = *(const float4*)(fi + (size_t)(row - NU) * DD + kc + ac4);
            }
        }
        fh = f; gh = g;
    };
    auto ldW = [&](int kc) {
        w1h = *(const float4*)(g_W1t + (size_t)(kc + wk) * DD + wseg);
        w2h = *(const float4*)(g_W2t + (size_t)(kc + wk) * DD + wseg);
    };
    auto stage = [&](int buf) {
        float4 f = fh, g = gh;
        float4 a, z;
        a.x = f.x + g.x; a.y = f.y + g.y; a.z = f.z + g.z; a.w = f.w + g.w;
        z.x = g.x * f.x; z.y = g.y * f.y; z.z = g.z * f.z; z.w = g.w * f.w;
        *(float4*)&As[buf][ar][ac4] = a;
        *(float4*)&Zs[buf][ar][ac4] = z;
        *(float4*)&w1c[buf][wk][wseg] = w1h;
        *(float4*)&w2c[buf][wk][wseg] = w2h;
    };

    u64 acc[8][4];   // 8 rows x 4 column-pairs (f32x2)
#pragma unroll
    for (int i = 0; i < 8; i++)
#pragma unroll
        for (int j = 0; j < 4; j++) acc[i][j] = 0ull;

    // prologue: chunk 0 staged to buf0; chunk 1 held in regs
    ldA(0); ldW(0); stage(0);
    ldA(8); ldW(8);
    __syncthreads();

    for (int c = 0; c < 16; c++) {
        int cur = c & 1, nb = 1 - cur;
        if (c < 15) {
            stage(nb);                       // write held chunk c+1
            if (c < 14) { ldA((c + 2) * 8); ldW((c + 2) * 8); }   // issue loads for c+2
        }
#pragma unroll
        for (int k = 0; k < 8; k++) {
            // proven float4 smem loads, then explicit packs (no reinterpret-cast loads)
            float wa[8], wb[8];
            *(float4*)&wa[0] = *(const float4*)&w1c[cur][k][og * 8];
            *(float4*)&wa[4] = *(const float4*)&w1c[cur][k][og * 8 + 4];
            *(float4*)&wb[0] = *(const float4*)&w2c[cur][k][og * 8];
            *(float4*)&wb[4] = *(const float4*)&w2c[cur][k][og * 8 + 4];
            u64 wp[4], vp[4];
#pragma unroll
            for (int jp = 0; jp < 4; jp++) {
                wp[jp] = pk(wa[2 * jp], wa[2 * jp + 1]);
                vp[jp] = pk(wb[2 * jp], wb[2 * jp + 1]);
            }
#pragma unroll
            for (int i = 0; i < 8; i++) {
                u64 a2 = pk2(As[cur][eg * 8 + i][k]);
                u64 z2 = pk2(Zs[cur][eg * 8 + i][k]);
                FFMA2(acc[i][0], a2, wp[0]);
                FFMA2(acc[i][1], a2, wp[1]);
                FFMA2(acc[i][2], a2, wp[2]);
                FFMA2(acc[i][3], a2, wp[3]);
                FFMA2(acc[i][0], z2, vp[0]);
                FFMA2(acc[i][1], z2, vp[1]);
                FFMA2(acc[i][2], z2, vp[2]);
                FFMA2(acc[i][3], z2, vp[3]);
            }
        }
        if (c < 15) __syncthreads();
    }

    // epilogue: bias, leaky, row-sumsq via 16-lane butterfly (og groups are half-warps)
    const int co = og * 8;
#pragma unroll
    for (int i = 0; i < 8; i++) {
        int r = eg * 8 + i;
        int row = rowBase + r;
        float sv = srow[r];
        float ssq = 0.f;
        float vals[8];
#pragma unroll
        for (int jp = 0; jp < 4; jp++) {
            float lo, hi;
            asm("mov.b64 {%0, %1}, %2;" : "=f"(lo), "=f"(hi) : "l"(acc[i][jp]));
            float v0 = leakyf(lo + b1s[co + 2 * jp]     + sv * bsum[co + 2 * jp]);
            float v1 = leakyf(hi + b1s[co + 2 * jp + 1] + sv * bsum[co + 2 * jp + 1]);
            vals[2 * jp] = v0; vals[2 * jp + 1] = v1;
            ssq += v0 * v0 + v1 * v1;
        }
#pragma unroll
        for (int m = 8; m > 0; m >>= 1)
            ssq += __shfl_xor_sync(0xffffffffu, ssq, m);
        if (row < NT) {
            float inv = 1.f / fmaxf(sqrtf(ssq), 1e-12f);
            float o8[8];
#pragma unroll
            for (int j = 0; j < 8; j++) o8[j] = vals[j] * inv;
            float* ho = out + (size_t)row * DD + co;
            *(float4*)ho       = *(float4*)&o8[0];
            *(float4*)(ho + 4) = *(float4*)&o8[4];
        }
    }
}

// ---------------- launch ----------------
extern "C" void kernel_launch(void* const* d_in, const int* in_sizes, int n_in,
                              void* d_out, int out_size) {
    const float* fu   = (const float*)d_in[0];
    const float* fi   = (const float*)d_in[1];
    const int*   src  = (const int*)d_in[2];
    const int*   dst  = (const int*)d_in[3];
    const float* nui  = (const float*)d_in[4];
    const float* niu  = (const float*)d_in[5];
    const float* W1   = (const float*)d_in[6];
    const float* b1   = (const float*)d_in[7];
    const float* W2   = (const float*)d_in[8];
    const float* b2   = (const float*)d_in[9];
    const float* attn = (const float*)d_in[10];
    float* out = (float*)d_out;

    k_zero<<<(NU + 255) / 256, 256>>>();
    k_count<<<EE / 256, 256>>>(src, dst);
    k_scan<<<2, 1024>>>();
    k_attn<<<(NT * 32 + 255) / 256, 256>>>(fu, fi, attn);
    k_prep<<<(DD * DD + 255) / 256, 256>>>(W1, W2);
    k_permute<<<EE / 256, 256>>>(src, dst, nui, niu);
    k_gather<<<(NT * 32 + 255) / 256, 256>>>(fu, fi);
    k_fused<<<(NT + 127) / 128, 256>>>(fu, fi, b1, b2, out);
}

// round 11
// speedup vs baseline: 4.8026x; 1.1421x over previous
#include <cuda_runtime.h>
#include <math.h>

#define NU 50000
#define NI 50000
#define DD 128
#define EE 800000
#define NT (NU + NI)

// ---------------- scratch ----------------
__device__ int      g_cnt_i[NI], g_cnt_u[NU];
__device__ int      g_base_i[NI + 1], g_base_u[NU + 1];
__device__ int      g_cur_i[NI], g_cur_u[NU];
__device__ int2     g_pair_i[EE], g_pair_u[EE];
__device__ float    g_Gu[NU * DD], g_Gi[NI * DD]; // aggregated (alpha-normalized) features
__device__ float    g_Su[NU], g_Si[NI];           // sum of weights per node
__device__ float    g_as_u[NU], g_ad_u[NU];
__device__ float    g_as_i[NI], g_ad_i[NI];
__device__ unsigned g_Whi[2 * DD * DD], g_Wlo[2 * DD * DD]; // tf32 hi/lo of [W1t;W2t], k-major

__device__ __forceinline__ float leakyf(float x) { return x >= 0.f ? x : 0.2f * x; }

__device__ __forceinline__ void split_tf32(float x, unsigned& hi, unsigned& lo) {
    asm("cvt.rna.tf32.f32 %0, %1;" : "=r"(hi) : "f"(x));
    float l = x - __uint_as_float(hi);
    asm("cvt.rna.tf32.f32 %0, %1;" : "=r"(lo) : "f"(l));
}

#define MMA_TF32(c, a, b0_, b1_) \
    asm("mma.sync.aligned.m16n8k8.row.col.f32.tf32.tf32.f32 " \
        "{%0,%1,%2,%3},{%4,%5,%6,%7},{%8,%9},{%0,%1,%2,%3};" \
        : "+f"((c)[0]), "+f"((c)[1]), "+f"((c)[2]), "+f"((c)[3]) \
        : "r"((a)[0]), "r"((a)[1]), "r"((a)[2]), "r"((a)[3]), "r"(b0_), "r"(b1_))

// ---------------- K0: zero counters ----------------
__global__ void k_zero() {
    int i = blockIdx.x * blockDim.x + threadIdx.x;
    if (i < NU) { g_cnt_i[i] = 0; g_cnt_u[i] = 0; }
}

// ---------------- K1: degree histograms ----------------
__global__ void k_count(const int* __restrict__ src, const int* __restrict__ dst) {
    int e = blockIdx.x * blockDim.x + threadIdx.x;
    if (e >= EE) return;
    atomicAdd(&g_cnt_i[dst[e]], 1);
    atomicAdd(&g_cnt_u[src[e]], 1);
}

// ---------------- K2: exclusive scan (2 blocks: 0=item, 1=user) ----------------
__global__ __launch_bounds__(1024) void k_scan() {
    const int N = NU;               // == NI
    int* cnt  = blockIdx.x ? g_cnt_u  : g_cnt_i;
    int* base = blockIdx.x ? g_base_u : g_base_i;
    int* cur  = blockIdx.x ? g_cur_u  : g_cur_i;
    __shared__ int part[1024];
    int t = threadIdx.x;
    const int C = (N + 1023) / 1024;
    int lo = t * C, hi = min(lo + C, N);
    int s = 0;
    for (int i = lo; i < hi; i++) s += cnt[i];
    part[t] = s;
    __syncthreads();
    for (int off = 1; off < 1024; off <<= 1) {
        int add = (t >= off) ? part[t - off] : 0;
        __syncthreads();
        part[t] += add;
        __syncthreads();
    }
    int run = (t == 0) ? 0 : part[t - 1];
    for (int i = lo; i < hi; i++) {
        int c = cnt[i];
        base[i] = run; cur[i] = run;
        run += c;
    }
    if (t == 1023) base[N] = run;
}

// ---------------- K3: per-node attention dots ----------------
__global__ __launch_bounds__(256) void k_attn(const float* __restrict__ fu,
                                              const float* __restrict__ fi,
                                              const float* __restrict__ attn) {
    __shared__ float at[256];
    int t = threadIdx.x;
    at[t] = attn[t];
    __syncthreads();
    int gwarp = (blockIdx.x * 256 + t) >> 5;
    int lane = t & 31;
    if (gwarp >= NT) return;
    const float* f = (gwarp < NU) ? (fu + (size_t)gwarp * DD)
                                  : (fi + (size_t)(gwarp - NU) * DD);
    float4 v = *(const float4*)(f + lane * 4);
    float4 a1 = *(const float4*)&at[lane * 4];
    float4 a2 = *(const float4*)&at[128 + lane * 4];
    float s = v.x * a1.x + v.y * a1.y + v.z * a1.z + v.w * a1.w;
    float d = v.x * a2.x + v.y * a2.y + v.z * a2.z + v.w * a2.w;
#pragma unroll
    for (int m = 16; m > 0; m >>= 1) {
        s += __shfl_xor_sync(0xffffffffu, s, m);
        d += __shfl_xor_sync(0xffffffffu, d, m);
    }
    if (lane == 0) {
        if (gwarp < NU) { g_as_u[gwarp] = s; g_ad_u[gwarp] = d; }
        else            { g_as_i[gwarp - NU] = s; g_ad_i[gwarp - NU] = d; }
    }
}

// ---------------- K4: split weights to tf32 hi/lo, k-major concat [W1t;W2t] ----------------
__global__ void k_prep(const float* __restrict__ W1, const float* __restrict__ W2) {
    int idx = blockIdx.x * 256 + threadIdx.x;   // k*128 + o
    if (idx >= 2 * DD * DD) return;
    int k = idx >> 7, o = idx & 127;
    float w = (k < DD) ? W1[o * DD + k] : W2[o * DD + (k - DD)];
    unsigned hi, lo;
    split_tf32(w, hi, lo);
    g_Whi[idx] = hi;
    g_Wlo[idx] = lo;
}

// ---------------- K5: permute edges into CSR pair lists ----------------
__global__ void k_permute(const int* __restrict__ src, const int* __restrict__ dst,
                          const float* __restrict__ nui, const float* __restrict__ niu) {
    int e = blockIdx.x * blockDim.x + threadIdx.x;
    if (e >= EE) return;
    int s = src[e], d = dst[e];
    int pi = atomicAdd(&g_cur_i[d], 1);
    g_pair_i[pi] = make_int2(s, __float_as_int(nui[e]));
    int pu = atomicAdd(&g_cur_u[s], 1);
    g_pair_u[pu] = make_int2(d, __float_as_int(niu[e]));
}

// ---------------- K6: gather — per-node register aggregation (softmax fused) ----------------
// (exact code that passed at 423.4us)
__global__ __launch_bounds__(256) void k_gather(const float* __restrict__ fu,
                                                const float* __restrict__ fi) {
    int w = (blockIdx.x * 256 + threadIdx.x) >> 5;
    int lane = threadIdx.x & 31;
    if (w >= NT) return;
    bool item = (w < NI);
    int n = item ? w : (w - NI);
    int beg = item ? g_base_i[n] : g_base_u[n];
    int end = item ? g_base_i[n + 1] : g_base_u[n + 1];
    const int2* __restrict__ pairs = item ? g_pair_i : g_pair_u;
    const float* __restrict__ as_arr = item ? g_as_u : g_as_i;
    const float* __restrict__ feat   = item ? fu : fi;
    float adv = item ? g_ad_i[n] : g_ad_u[n];

    float4 acc = make_float4(0.f, 0.f, 0.f, 0.f);
    float aden = 0.f, aS = 0.f;

    int e = beg;
    int2 pr = (e < end) ? pairs[e] : make_int2(0, 0);
    while (e < end) {
        int s = pr.x;
        float nrm = __int_as_float(pr.y);
        int2 prn = make_int2(0, 0);
        if (e + 1 < end) prn = pairs[e + 1];
        float asv = as_arr[s];
        float4 x = *(const float4*)(feat + (size_t)s * DD + lane * 4);
        float ex = __expf(leakyf(asv + adv));
        float wn = ex * nrm;
        acc.x += wn * x.x; acc.y += wn * x.y; acc.z += wn * x.z; acc.w += wn * x.w;
        aden += ex; aS += wn;
        pr = prn; e++;
    }
    float inv = (aden > 0.f) ? __fdividef(1.f, aden) : 0.f;
    float* G = item ? (g_Gi + (size_t)n * DD) : (g_Gu + (size_t)n * DD);
    *(float4*)(G + lane * 4) = make_float4(acc.x * inv, acc.y * inv, acc.z * inv, acc.w * inv);
    if (lane == 0) (item ? g_Si : g_Su)[n] = aS * inv;
}

// ---------------- K7: fused dense via 3xTF32 mma.sync ----------------
// out = normalize(leaky([A|Z] @ [W1t;W2t] + b1 + S*(b1+b2))), A = feat+G, Z = G∘feat.
// Block: 128 rows x 128 cols, K=256 in 16 chunks of 16. 8 warps = 4(M) x 2(N).
// Per warp: M=32, N=64 -> 2x8 m16n8k8 tiles, 3 MMAs each (hi*hi + hi*lo + lo*hi).
__global__ __launch_bounds__(256) void k_fused(const float* __restrict__ fu,
                                               const float* __restrict__ fi,
                                               const float* __restrict__ b1,
                                               const float* __restrict__ b2,
                                               float* __restrict__ out) {
    __shared__ float    az[128][20];     // fp32 A/Z chunk (stride 20: conflict-free frags)
    __shared__ unsigned whi[16][136];    // tf32-hi W chunk (stride 136: conflict-free frags)
    __shared__ unsigned wlo[16][136];
    __shared__ float    b1s[128], bsum[128], srow[128];
    __shared__ float    ssq_sm[128][2];

    const int t = threadIdx.x;
    const int lane = t & 31;
    const int gid = lane >> 2, tid = lane & 3;
    const int warpId = t >> 5;
    const int warpM = warpId & 3;        // 4 M-warps
    const int warpN = warpId >> 2;       // 2 N-warps
    const int rowBase = blockIdx.x * 128;

    if (t < 128) {
        float v1 = b1[t], v2 = b2[t];
        b1s[t] = v1;
        bsum[t] = v1 + v2;
        int row = rowBase + t;
        float sv = 0.f;
        if (row < NT) sv = (row < NU) ? g_Su[row] : g_Si[row - NU];
        srow[t] = sv;
    }

    float acc[2][8][4];
#pragma unroll
    for (int mt = 0; mt < 2; mt++)
#pragma unroll
        for (int nt = 0; nt < 8; nt++)
#pragma unroll
            for (int r = 0; r < 4; r++) acc[mt][nt][r] = 0.f;

    for (int c = 0; c < 16; c++) {
        if (c) __syncthreads();
        // stage A/Z chunk: 128 rows x 16 cols = 512 float4
#pragma unroll
        for (int i = 0; i < 2; i++) {
            int idx = t + i * 256;
            int r = idx >> 2, c4 = (idx & 3) * 4;
            int row = rowBase + r;
            float4 f = make_float4(0.f, 0.f, 0.f, 0.f);
            float4 g = make_float4(0.f, 0.f, 0.f, 0.f);
            int kcol = (c < 8) ? (c * 16 + c4) : ((c - 8) * 16 + c4);
            if (row < NT) {
                if (row < NU) {
                    g = *(const float4*)(g_Gu + (size_t)row * DD + kcol);
                    f = *(const float4*)(fu + (size_t)row * DD + kcol);
                } else {
                    g = *(const float4*)(g_Gi + (size_t)(row - NU) * DD + kcol);
                    f = *(const float4*)(fi + (size_t)(row - NU) * DD + kcol);
                }
            }
            float4 v;
            if (c < 8) { v.x = f.x + g.x; v.y = f.y + g.y; v.z = f.z + g.z; v.w = f.w + g.w; }
            else       { v.x = f.x * g.x; v.y = f.y * g.y; v.z = f.z * g.z; v.w = f.w * g.w; }
            *(float4*)&az[r][c4] = v;
        }
        // stage W hi/lo chunk: 16 k-rows x 128 cols each = 512 uint4 each
#pragma unroll
        for (int i = 0; i < 2; i++) {
            int idx = t + i * 256;
            int k = idx >> 5, seg = (idx & 31) * 4;
            *(uint4*)&whi[k][seg] = *(const uint4*)&g_Whi[(size_t)(c * 16 + k) * DD + seg];
            *(uint4*)&wlo[k][seg] = *(const uint4*)&g_Wlo[(size_t)(c * 16 + k) * DD + seg];
        }
        __syncthreads();

#pragma unroll
        for (int ks = 0; ks < 2; ks++) {
            unsigned ah[2][4], al[2][4];
#pragma unroll
            for (int mt = 0; mt < 2; mt++) {
                int rb = warpM * 32 + mt * 16;
                int col = ks * 8 + tid;
                split_tf32(az[rb + gid][col],         ah[mt][0], al[mt][0]);
                split_tf32(az[rb + 8 + gid][col],     ah[mt][1], al[mt][1]);
                split_tf32(az[rb + gid][col + 4],     ah[mt][2], al[mt][2]);
                split_tf32(az[rb + 8 + gid][col + 4], ah[mt][3], al[mt][3]);
            }
#pragma unroll
            for (int nt = 0; nt < 8; nt++) {
                int cb = warpN * 64 + nt * 8 + gid;
                int kr = ks * 8 + tid;
                unsigned bh0 = whi[kr][cb], bh1 = whi[kr + 4][cb];
                unsigned bl0 = wlo[kr][cb], bl1 = wlo[kr + 4][cb];
#pragma unroll
                for (int mt = 0; mt < 2; mt++) {
                    MMA_TF32(acc[mt][nt], ah[mt], bh0, bh1);
                    MMA_TF32(acc[mt][nt], ah[mt], bl0, bl1);
                    MMA_TF32(acc[mt][nt], al[mt], bh0, bh1);
                }
            }
        }
    }

    // epilogue: bias + leaky + row sum-of-squares
    float ssqp[4] = {0.f, 0.f, 0.f, 0.f};
#pragma unroll
    for (int mt = 0; mt < 2; mt++) {
        int r0 = warpM * 32 + mt * 16 + gid;
        float s0 = srow[r0], s1 = srow[r0 + 8];
#pragma unroll
        for (int nt = 0; nt < 8; nt++) {
            int cc = warpN * 64 + nt * 8 + tid * 2;
            float bb0 = b1s[cc], bb1 = b1s[cc + 1];
            float bs0 = bsum[cc], bs1 = bsum[cc + 1];
            float v0 = leakyf(acc[mt][nt][0] + bb0 + s0 * bs0);
            float v1 = leakyf(acc[mt][nt][1] + bb1 + s0 * bs1);
            float v2 = leakyf(acc[mt][nt][2] + bb0 + s1 * bs0);
            float v3 = leakyf(acc[mt][nt][3] + bb1 + s1 * bs1);
            acc[mt][nt][0] = v0; acc[mt][nt][1] = v1;
            acc[mt][nt][2] = v2; acc[mt][nt][3] = v3;
            ssqp[mt * 2]     += v0 * v0 + v1 * v1;
            ssqp[mt * 2 + 1] += v2 * v2 + v3 * v3;
        }
    }
#pragma unroll
    for (int j = 0; j < 4; j++) {
        ssqp[j] += __shfl_xor_sync(0xffffffffu, ssqp[j], 1);
        ssqp[j] += __shfl_xor_sync(0xffffffffu, ssqp[j], 2);
    }
    if (tid == 0) {
#pragma unroll
        for (int mt = 0; mt < 2; mt++) {
            ssq_sm[warpM * 32 + mt * 16 + gid][warpN]     = ssqp[mt * 2];
            ssq_sm[warpM * 32 + mt * 16 + 8 + gid][warpN] = ssqp[mt * 2 + 1];
        }
    }
    __syncthreads();

#pragma unroll
    for (int mt = 0; mt < 2; mt++) {
        int lr0 = warpM * 32 + mt * 16 + gid, lr1 = lr0 + 8;
        float inv0 = 1.f / fmaxf(sqrtf(ssq_sm[lr0][0] + ssq_sm[lr0][1]), 1e-12f);
        float inv1 = 1.f / fmaxf(sqrtf(ssq_sm[lr1][0] + ssq_sm[lr1][1]), 1e-12f);
        int row0 = rowBase + lr0, row1 = rowBase + lr1;
#pragma unroll
        for (int nt = 0; nt < 8; nt++) {
            int cc = warpN * 64 + nt * 8 + tid * 2;
            if (row0 < NT) {
                float2 o0 = make_float2(acc[mt][nt][0] * inv0, acc[mt][nt][1] * inv0);
                *(float2*)(out + (size_t)row0 * DD + cc) = o0;
            }
            if (row1 < NT) {
                float2 o1 = make_float2(acc[mt][nt][2] * inv1, acc[mt][nt][3] * inv1);
                *(float2*)(out + (size_t)row1 * DD + cc) = o1;
            }
        }
    }
}

// ---------------- launch ----------------
extern "C" void kernel_launch(void* const* d_in, const int* in_sizes, int n_in,
                              void* d_out, int out_size) {
    const float* fu   = (const float*)d_in[0];
    const float* fi   = (const float*)d_in[1];
    const int*   src  = (const int*)d_in[2];
    const int*   dst  = (const int*)d_in[3];
    const float* nui  = (const float*)d_in[4];
    const float* niu  = (const float*)d_in[5];
    const float* W1   = (const float*)d_in[6];
    const float* b1   = (const float*)d_in[7];
    const float* W2   = (const float*)d_in[8];
    const float* b2   = (const float*)d_in[9];
    const float* attn = (const float*)d_in[10];
    float* out = (float*)d_out;

    k_zero<<<(NU + 255) / 256, 256>>>();
    k_count<<<EE / 256, 256>>>(src, dst);
    k_scan<<<2, 1024>>>();
    k_attn<<<(NT * 32 + 255) / 256, 256>>>(fu, fi, attn);
    k_prep<<<(2 * DD * DD + 255) / 256, 256>>>(W1, W2);
    k_permute<<<EE / 256, 256>>>(src, dst, nui, niu);
    k_gather<<<(NT * 32 + 255) / 256, 256>>>(fu, fi);
    k_fused<<<(NT + 127) / 128, 256>>>(fu, fi, b1, b2, out);
}